// round 10
// baseline (speedup 1.0000x reference)
#include <cuda_runtime.h>

#define BB 16
#define NN 4096
#define S1V 512
#define S2V 256
#define KV 32
#define EPSF 1e-5f

// ---------------- scratch (static device globals; no allocation) ----------------
__device__ float g_zbuf[33554432];            // 128 MB ping
__device__ float g_abuf[33554432];            // 128 MB pong
__device__ float g_f[BB * NN * 64];           // features after point_cbr x2  (B,N,64)
__device__ float g_f1[BB * S1V * 128];        // sg1 output features (B,S1,128)
__device__ float g_cx[BB * NN], g_cy[BB * NN], g_cz[BB * NN];     // coords SoA
__device__ float g_c2x[BB * S1V], g_c2y[BB * S1V], g_c2z[BB * S1V];
__device__ int   g_fidx1[BB * S1V], g_fidx2[BB * S2V];
__device__ int   g_knn1[BB * S1V * KV], g_knn2[BB * S2V * KV];
__device__ float g_sum[256], g_sumsq[256], g_scale[256], g_shift[256];

__device__ __forceinline__ float* buf_sel(int w) {
    return (w == 0) ? g_zbuf : ((w == 1) ? g_abuf : g_f);
}

// ---------------- coords prep ----------------
__global__ void prep_coords(const float* __restrict__ x) {
    int i = blockIdx.x * 256 + threadIdx.x;          // BB*NN total
    int b = i >> 12, n = i & 4095;
    const float* xb = x + (size_t)b * 3 * NN;
    g_cx[i] = xb[n];
    g_cy[i] = xb[NN + n];
    g_cz[i] = xb[2 * NN + n];
}

// ---------------- point_cbr stage 1: z[r,o] = sum_c w1[o,c] x[b,c,n] ----------------
__global__ void cbr1_kernel(const float* __restrict__ x, const float* __restrict__ w1) {
    int idx = blockIdx.x * 256 + threadIdx.x;        // (B*N)*64 total
    int r = idx >> 6, o = idx & 63;
    int b = r >> 12, n = r & 4095;
    const float* xb = x + (size_t)b * 3 * NN;
    float v = w1[o * 3 + 0] * xb[n] + w1[o * 3 + 1] * xb[NN + n] + w1[o * 3 + 2] * xb[2 * NN + n];
    g_zbuf[idx] = v;
}

// ---------------- point_cbr stage 2: g_f[r,o] = sum_c yhat[r,c] w2[o,c] ----------------
__global__ void cbr2_kernel(const float* __restrict__ w2) {
    __shared__ float ys[4][64];
    __shared__ float wst[64 * 64];    // transposed: wst[c*64+o] = w2[o*64+c]
    int tid = threadIdx.x;            // 256
    int r0 = blockIdx.x * 4;
    for (int j = tid; j < 4096; j += 256) {
        int o = j >> 6, c = j & 63;
        wst[c * 64 + o] = w2[j];
    }
    ((float*)ys)[tid] = g_zbuf[r0 * 64 + tid];
    __syncthreads();
    int rl = tid >> 6, o = tid & 63;
    float acc = 0.f;
#pragma unroll 16
    for (int c = 0; c < 64; c++) acc += ys[rl][c] * wst[c * 64 + o];
    g_f[(r0 + rl) * 64 + o] = acc;
}

// ---------------- BN stats / finalize / apply ----------------
__global__ void zero_stats() { g_sum[threadIdx.x] = 0.f; g_sumsq[threadIdx.x] = 0.f; }

__global__ void stats_kernel(int which, int total, int O) {
    const float* z = buf_sel(which);
    int gt = blockIdx.x * 256 + threadIdx.x;
    int stride = gridDim.x * 256;
    float s = 0.f, q = 0.f;
    for (int i = gt; i < total; i += stride) { float v = z[i]; s += v; q += v * v; }
    __shared__ float bs[256], bq[256];
    bs[threadIdx.x] = s; bq[threadIdx.x] = q;
    __syncthreads();
    if (threadIdx.x < O) {
        for (int j = threadIdx.x + O; j < 256; j += O) { s += bs[j]; q += bq[j]; }
        atomicAdd(&g_sum[threadIdx.x], s);
        atomicAdd(&g_sumsq[threadIdx.x], q);
    }
}

__global__ void finalize_stats(const float* __restrict__ g, const float* __restrict__ bias, float invR) {
    int o = threadIdx.x;
    float m = g_sum[o] * invR;
    float v = g_sumsq[o] * invR - m * m;
    float rstd = rsqrtf(v + EPSF);
    float sc = g[o] * rstd;
    g_scale[o] = sc;
    g_shift[o] = bias[o] - m * sc;
}

__global__ void bnrelu_kernel(int which, int total, int omask) {
    float* z = buf_sel(which);
    int i = blockIdx.x * 256 + threadIdx.x;
    if (i >= total) return;
    int o = i & omask;
    float v = z[i] * g_scale[o] + g_shift[o];
    z[i] = v > 0.f ? v : 0.f;
}

// ---------------- FPS (matches jax scan: emit far, update dist, argmax) ----------------
template <int NPTS, int NSAMP, int TPB, int STAGE>
__global__ void fps_kernel() {
    constexpr int PPT = NPTS / TPB;
    const float* cx = (STAGE == 0) ? g_cx : g_c2x;
    const float* cy = (STAGE == 0) ? g_cy : g_c2y;
    const float* cz = (STAGE == 0) ? g_cz : g_c2z;
    int* fidx = (STAGE == 0) ? g_fidx1 : g_fidx2;
    int b = blockIdx.x, tid = threadIdx.x;
    const float* bx = cx + b * NPTS;
    const float* by = cy + b * NPTS;
    const float* bz = cz + b * NPTS;
    float px[PPT], py[PPT], pz[PPT], dist[PPT];
#pragma unroll
    for (int t = 0; t < PPT; t++) {
        int n = tid + t * TPB;
        px[t] = bx[n]; py[t] = by[n]; pz[t] = bz[n];
        dist[t] = 1e10f;
    }
    __shared__ float wv[TPB / 32];
    __shared__ int wi[TPB / 32];
    __shared__ int s_far;
    int far = 0;
    for (int s = 0; s < NSAMP; s++) {
        if (tid == 0) fidx[b * NSAMP + s] = far;
        float fx = bx[far], fy = by[far], fz = bz[far];
        float bv = -1.0f; int bi = 0x7fffffff;
#pragma unroll
        for (int t = 0; t < PPT; t++) {
            float dx = __fsub_rn(px[t], fx);
            float dy = __fsub_rn(py[t], fy);
            float dz = __fsub_rn(pz[t], fz);
            float d = __fadd_rn(__fadd_rn(__fmul_rn(dx, dx), __fmul_rn(dy, dy)), __fmul_rn(dz, dz));
            float nd = fminf(dist[t], d);
            dist[t] = nd;
            int n = tid + t * TPB;
            if (nd > bv) { bv = nd; bi = n; }   // ascending n: strict > keeps lowest idx on tie
        }
#pragma unroll
        for (int off = 16; off > 0; off >>= 1) {
            float ov = __shfl_down_sync(0xffffffffu, bv, off);
            int oi = __shfl_down_sync(0xffffffffu, bi, off);
            if (ov > bv || (ov == bv && oi < bi)) { bv = ov; bi = oi; }
        }
        if ((tid & 31) == 0) { wv[tid >> 5] = bv; wi[tid >> 5] = bi; }
        __syncthreads();
        if (tid < 32) {
            constexpr int NW = TPB / 32;
            float v2 = (tid < NW) ? wv[tid] : -2.0f;
            int i2 = (tid < NW) ? wi[tid] : 0x7fffffff;
#pragma unroll
            for (int off = 16; off > 0; off >>= 1) {
                float ov = __shfl_down_sync(0xffffffffu, v2, off);
                int oi = __shfl_down_sync(0xffffffffu, i2, off);
                if (ov > v2 || (ov == v2 && oi < i2)) { v2 = ov; i2 = oi; }
            }
            if (tid == 0) s_far = i2;
        }
        __syncthreads();
        far = s_far;
    }
}

// ---------------- gather coords of sg1 sampled points ----------------
__global__ void gather_c2() {
    int i = blockIdx.x * 256 + threadIdx.x;   // BB*S1V
    int b = i >> 9;
    int id = g_fidx1[i];
    g_c2x[i] = g_cx[b * NN + id];
    g_c2y[i] = g_cy[b * NN + id];
    g_c2z[i] = g_cz[b * NN + id];
}

// ---------------- KNN: warp-resident top-32 (smallest d), replace-max insertion ----------------
template <int NPTS, int S, int STAGE>
__global__ void knn_kernel() {
    const float* cx = (STAGE == 0) ? g_cx : g_c2x;
    const float* cy = (STAGE == 0) ? g_cy : g_c2y;
    const float* cz = (STAGE == 0) ? g_cz : g_c2z;
    const int* fidx = (STAGE == 0) ? g_fidx1 : g_fidx2;
    int* knn = (STAGE == 0) ? g_knn1 : g_knn2;

    int gw = (blockIdx.x * blockDim.x + threadIdx.x) >> 5;   // global warp = centroid
    int lane = threadIdx.x & 31;
    int b = gw / S;
    const float* bx = cx + b * NPTS;
    const float* by = cy + b * NPTS;
    const float* bz = cz + b * NPTS;
    int ci = fidx[gw];
    float fx = bx[ci], fy = by[ci], fz = bz[ci];
    float fn = (fx * fx + fy * fy) + fz * fz;

    auto distf = [&](int n) {
        float xx = bx[n], yy = by[n], zz = bz[n];
        float nb = (xx * xx + yy * yy) + zz * zz;
        return fn + nb - 2.0f * (fx * xx + fy * yy + fz * zz);
    };

    float bd = distf(lane);
    int bidx = lane;

    float kv; int kl;   // current max of the 32-best set + owning lane
    {
        kv = bd; kl = lane;
#pragma unroll
        for (int off = 16; off > 0; off >>= 1) {
            float ov = __shfl_xor_sync(0xffffffffu, kv, off);
            int ol = __shfl_xor_sync(0xffffffffu, kl, off);
            if (ov > kv || (ov == kv && ol < kl)) { kv = ov; kl = ol; }
        }
    }
    for (int base = 32; base < NPTS; base += 32) {
        int n = base + lane;
        float d = distf(n);
        unsigned m = __ballot_sync(0xffffffffu, d < kv);
        while (m) {
            int src = __ffs(m) - 1;
            m &= m - 1;
            float dc = __shfl_sync(0xffffffffu, d, src);
            int nc = __shfl_sync(0xffffffffu, n, src);
            if (dc < kv) {
                if (lane == kl) { bd = dc; bidx = nc; }
                kv = bd; kl = lane;
#pragma unroll
                for (int off = 16; off > 0; off >>= 1) {
                    float ov = __shfl_xor_sync(0xffffffffu, kv, off);
                    int ol = __shfl_xor_sync(0xffffffffu, kl, off);
                    if (ov > kv || (ov == kv && ol < kl)) { kv = ov; kl = ol; }
                }
            }
        }
    }
    knn[gw * KV + lane] = bidx;
}

// ---------------- build A matrices: rows = (b,s,k), cols = [nb - center | center] ----------------
__global__ void buildA1() {
    int bs = blockIdx.x;                 // BB*S1V
    int tid = threadIdx.x;               // 256
    int b = bs >> 9;
    __shared__ float cf[64];
    int fid = g_fidx1[bs];
    if (tid < 64) cf[tid] = g_f[(b * NN + fid) * 64 + tid];
    __syncthreads();
    int c = tid & 63;
    for (int k = tid >> 6; k < KV; k += 4) {
        int nb = g_knn1[bs * KV + k];
        float fv = g_f[(b * NN + nb) * 64 + c];
        size_t row = (size_t)bs * KV + k;
        g_abuf[row * 128 + c] = fv - cf[c];
        g_abuf[row * 128 + 64 + c] = cf[c];
    }
}

__global__ void buildA2() {
    int bs = blockIdx.x;                 // BB*S2V
    int tid = threadIdx.x;               // 256
    int b = bs >> 8;
    __shared__ float cf[128];
    int fid = g_fidx2[bs];
    if (tid < 128) cf[tid] = g_f1[(b * S1V + fid) * 128 + tid];
    __syncthreads();
    int c = tid & 127;
    for (int k = tid >> 7; k < KV; k += 2) {
        int nb = g_knn2[bs * KV + k];
        float fv = g_f1[(b * S1V + nb) * 128 + c];
        size_t row = (size_t)bs * KV + k;
        g_abuf[row * 256 + c] = fv - cf[c];
        g_abuf[row * 256 + 128 + c] = cf[c];
    }
}

// ---------------- tiled SGEMM: C[r,o] = sum_c A[r,c] * W[o,c] ----------------
template <int CIN>
__global__ __launch_bounds__(256) void sgemm_kernel(int asel, const float* __restrict__ W,
                                                    int csel, int O) {
    const float* A = buf_sel(asel);
    float* C = buf_sel(csel);
    __shared__ float As[8][128];
    __shared__ float Bs[8][128];
    int tid = threadIdx.x;
    int brow = blockIdx.x * 128;
    int bcol = blockIdx.y * 128;
    int tx = tid & 15, ty = tid >> 4;
    float acc[8][8];
#pragma unroll
    for (int i = 0; i < 8; i++)
#pragma unroll
        for (int j = 0; j < 8; j++) acc[i][j] = 0.f;
    int lr = tid >> 1;
    int lc = (tid & 1) * 4;
    const float* Aptr = A + (size_t)(brow + lr) * CIN + lc;
    const float* Wptr = W + (size_t)(bcol + lr) * CIN + lc;
#pragma unroll 4
    for (int c0 = 0; c0 < CIN; c0 += 8) {
        float4 av = *(const float4*)(Aptr + c0);
        float4 wv = *(const float4*)(Wptr + c0);
        __syncthreads();
        As[lc + 0][lr] = av.x; As[lc + 1][lr] = av.y; As[lc + 2][lr] = av.z; As[lc + 3][lr] = av.w;
        Bs[lc + 0][lr] = wv.x; Bs[lc + 1][lr] = wv.y; Bs[lc + 2][lr] = wv.z; Bs[lc + 3][lr] = wv.w;
        __syncthreads();
#pragma unroll
        for (int k = 0; k < 8; k++) {
            float a[8], bv[8];
#pragma unroll
            for (int i = 0; i < 8; i++) a[i] = As[k][ty * 8 + i];
#pragma unroll
            for (int j = 0; j < 8; j++) bv[j] = Bs[k][tx * 8 + j];
#pragma unroll
            for (int i = 0; i < 8; i++)
#pragma unroll
                for (int j = 0; j < 8; j++) acc[i][j] += a[i] * bv[j];
        }
    }
#pragma unroll
    for (int i = 0; i < 8; i++) {
        int r = brow + ty * 8 + i;
        float4* cp = (float4*)(C + (size_t)r * O + bcol + tx * 8);
        cp[0] = make_float4(acc[i][0], acc[i][1], acc[i][2], acc[i][3]);
        cp[1] = make_float4(acc[i][4], acc[i][5], acc[i][6], acc[i][7]);
    }
}

// ---------------- max-pool over K ----------------
__global__ void maxpool1() {
    int bs = blockIdx.x;             // BB*S1V
    int o = threadIdx.x;             // 128
    const float* base = g_abuf + (size_t)bs * KV * 128;
    float m = base[o];
#pragma unroll
    for (int k = 1; k < KV; k++) m = fmaxf(m, base[k * 128 + o]);
    g_f1[bs * 128 + o] = m;
}

__global__ void maxpool2(float* __restrict__ out) {
    int bs = blockIdx.x;             // BB*S2V
    int o = threadIdx.x;             // 256
    int b = bs >> 8, s = bs & 255;
    const float* base = g_abuf + (size_t)bs * KV * 256;
    float m = base[o];
#pragma unroll
    for (int k = 1; k < KV; k++) m = fmaxf(m, base[k * 256 + o]);
    out[((size_t)b * 256 + o) * 256 + s] = m;
}

// ---------------- launch sequence ----------------
extern "C" void kernel_launch(void* const* d_in, const int* in_sizes, int n_in,
                              void* d_out, int out_size) {
    const float* x     = (const float*)d_in[0];
    const float* w1    = (const float*)d_in[1];
    const float* w2    = (const float*)d_in[2];
    const float* g1    = (const float*)d_in[3];
    const float* b1    = (const float*)d_in[4];
    const float* g2    = (const float*)d_in[5];
    const float* b2    = (const float*)d_in[6];
    const float* s1w1  = (const float*)d_in[7];
    const float* s1w2  = (const float*)d_in[8];
    const float* s1g1  = (const float*)d_in[9];
    const float* s1b1  = (const float*)d_in[10];
    const float* s1g2  = (const float*)d_in[11];
    const float* s1b2  = (const float*)d_in[12];
    const float* s2w1  = (const float*)d_in[13];
    const float* s2w2  = (const float*)d_in[14];
    const float* s2g1  = (const float*)d_in[15];
    const float* s2b1  = (const float*)d_in[16];
    const float* s2g2  = (const float*)d_in[17];
    const float* s2b2  = (const float*)d_in[18];
    float* out = (float*)d_out;

    const int RP = BB * NN;                 // 65536 pointwise rows
    const int R1 = BB * S1V * KV;           // 262144
    const int R2 = BB * S2V * KV;           // 131072

    // coords
    prep_coords<<<RP / 256, 256>>>(x);

    // point_cbr 1
    cbr1_kernel<<<RP * 64 / 256, 256>>>(x, w1);
    zero_stats<<<1, 256>>>();
    stats_kernel<<<512, 256>>>(0, RP * 64, 64);
    finalize_stats<<<1, 64>>>(g1, b1, 1.0f / RP);
    bnrelu_kernel<<<RP * 64 / 256, 256>>>(0, RP * 64, 63);

    // point_cbr 2 -> g_f
    cbr2_kernel<<<RP / 4, 256>>>(w2);
    zero_stats<<<1, 256>>>();
    stats_kernel<<<512, 256>>>(2, RP * 64, 64);
    finalize_stats<<<1, 64>>>(g2, b2, 1.0f / RP);
    bnrelu_kernel<<<RP * 64 / 256, 256>>>(2, RP * 64, 63);

    // sg1: FPS + gather + KNN + A-build
    fps_kernel<NN, S1V, 1024, 0><<<BB, 1024>>>();
    gather_c2<<<BB * S1V / 256, 256>>>();
    knn_kernel<NN, S1V, 0><<<BB * S1V / 4, 128>>>();
    buildA1<<<BB * S1V, 256>>>();

    // sg1 MLP layer 1: zbuf = A1 @ s1w1^T
    sgemm_kernel<128><<<dim3(R1 / 128, 1), 256>>>(1, s1w1, 0, 128);
    zero_stats<<<1, 256>>>();
    stats_kernel<<<512, 256>>>(0, R1 * 128, 128);
    finalize_stats<<<1, 128>>>(s1g1, s1b1, 1.0f / R1);
    bnrelu_kernel<<<R1 * 128 / 256, 256>>>(0, R1 * 128, 127);

    // sg1 MLP layer 2: abuf = y1 @ s1w2^T
    sgemm_kernel<128><<<dim3(R1 / 128, 1), 256>>>(0, s1w2, 1, 128);
    zero_stats<<<1, 256>>>();
    stats_kernel<<<512, 256>>>(1, R1 * 128, 128);
    finalize_stats<<<1, 128>>>(s1g2, s1b2, 1.0f / R1);
    bnrelu_kernel<<<R1 * 128 / 256, 256>>>(1, R1 * 128, 127);

    // sg1 max-pool -> g_f1
    maxpool1<<<BB * S1V, 128>>>();

    // sg2: FPS + KNN + A-build
    fps_kernel<S1V, S2V, 512, 1><<<BB, 512>>>();
    knn_kernel<S1V, S2V, 1><<<BB * S2V / 4, 128>>>();
    buildA2<<<BB * S2V, 256>>>();

    // sg2 MLP layer 1: zbuf = A2 @ s2w1^T
    sgemm_kernel<256><<<dim3(R2 / 128, 2), 256>>>(1, s2w1, 0, 256);
    zero_stats<<<1, 256>>>();
    stats_kernel<<<512, 256>>>(0, R2 * 256, 256);
    finalize_stats<<<1, 256>>>(s2g1, s2b1, 1.0f / R2);
    bnrelu_kernel<<<R2 * 256 / 256, 256>>>(0, R2 * 256, 255);

    // sg2 MLP layer 2: abuf = y1 @ s2w2^T
    sgemm_kernel<256><<<dim3(R2 / 128, 2), 256>>>(0, s2w2, 1, 256);
    zero_stats<<<1, 256>>>();
    stats_kernel<<<512, 256>>>(1, R2 * 256, 256);
    finalize_stats<<<1, 256>>>(s2g2, s2b2, 1.0f / R2);
    bnrelu_kernel<<<R2 * 256 / 256, 256>>>(1, R2 * 256, 255);

    // sg2 max-pool -> out (transposed to B, 256, S2)
    maxpool2<<<BB * S2V, 256>>>(out);
}

// round 11
// speedup vs baseline: 1.3758x; 1.3758x over previous
#include <cuda_runtime.h>

#define BB 16
#define NN 4096
#define S1V 512
#define S2V 256
#define KV 32
#define EPSF 1e-5f

// ---------------- scratch (static device globals; no allocation) ----------------
__device__ __align__(16) float g_zbuf[33554432];            // 128 MB ping
__device__ __align__(16) float g_abuf[33554432];            // 128 MB pong
__device__ __align__(16) float g_f[BB * NN * 64];           // raw cbr2 output (B,N,64)
__device__ __align__(16) float g_f1[BB * S1V * 128];        // sg1 final features (B,S1,128)
__device__ __align__(16) float g_cfeat1[BB * S1V * 64];     // bn-relu'd center feats sg1
__device__ __align__(16) float g_cfeat2[BB * S2V * 128];    // center feats sg2
__device__ __align__(16) float g_c1out[BB * S1V * 128];     // center @ wdiff1^T
__device__ __align__(16) float g_c2out[BB * S2V * 256];     // center @ wdiff2^T
__device__ __align__(16) float g_wdiff1[128 * 64];
__device__ __align__(16) float g_wdiff2[256 * 128];
__device__ float g_cx[BB * NN], g_cy[BB * NN], g_cz[BB * NN];     // coords SoA
__device__ float g_c2x[BB * S1V], g_c2y[BB * S1V], g_c2z[BB * S1V];
__device__ int   g_fidx1[BB * S1V], g_fidx2[BB * S2V];
__device__ int   g_knn1[BB * S1V * KV], g_knn2[BB * S2V * KV];
__device__ __align__(16) float g_sum[256], g_sumsq[256];
__device__ __align__(16) float g_scale[256], g_shift[256];

__device__ __forceinline__ float* buf_sel(int w) {
    switch (w) {
        case 0: return g_zbuf;
        case 1: return g_abuf;
        case 2: return g_f;
        case 3: return g_cfeat1;
        case 4: return g_cfeat2;
        case 5: return g_c1out;
        case 6: return g_c2out;
        case 7: return g_wdiff1;
        case 8: return g_wdiff2;
        case 9: return g_f1;
    }
    return g_zbuf;
}

// ---------------- coords prep ----------------
__global__ void prep_coords(const float* __restrict__ x) {
    int i = blockIdx.x * 256 + threadIdx.x;          // BB*NN total
    int b = i >> 12, n = i & 4095;
    const float* xb = x + (size_t)b * 3 * NN;
    g_cx[i] = xb[n];
    g_cy[i] = xb[NN + n];
    g_cz[i] = xb[2 * NN + n];
}

// ---------------- point_cbr stage 1 (raw, no BN) ----------------
__global__ void cbr1_kernel(const float* __restrict__ x, const float* __restrict__ w1) {
    int idx = blockIdx.x * 256 + threadIdx.x;        // (B*N)*64 total
    int r = idx >> 6, o = idx & 63;
    int b = r >> 12, n = r & 4095;
    const float* xb = x + (size_t)b * 3 * NN;
    float v = w1[o * 3 + 0] * xb[n] + w1[o * 3 + 1] * xb[NN + n] + w1[o * 3 + 2] * xb[2 * NN + n];
    g_zbuf[idx] = v;
}

// ---------------- point_cbr stage 2: bnrelu(zbuf) @ w2^T -> g_f (raw) ----------------
__global__ void cbr2_kernel(const float* __restrict__ w2) {
    __shared__ float ys[4][64];
    __shared__ float wst[64 * 64];    // transposed: wst[c*64+o] = w2[o*64+c]
    int tid = threadIdx.x;            // 256
    int r0 = blockIdx.x * 4;
    for (int j = tid; j < 4096; j += 256) {
        int o = j >> 6, c = j & 63;
        wst[c * 64 + o] = w2[j];
    }
    {
        int c = tid & 63;
        float v = g_zbuf[r0 * 64 + tid];
        v = fmaxf(v * g_scale[c] + g_shift[c], 0.f);
        ((float*)ys)[tid] = v;
    }
    __syncthreads();
    int rl = tid >> 6, o = tid & 63;
    float acc = 0.f;
#pragma unroll 16
    for (int c = 0; c < 64; c++) acc += ys[rl][c] * wst[c * 64 + o];
    g_f[(r0 + rl) * 64 + o] = acc;
}

// ---------------- BN stats / finalize ----------------
__global__ void zero_stats() { g_sum[threadIdx.x] = 0.f; g_sumsq[threadIdx.x] = 0.f; }

__global__ void stats_kernel(int which, int total, int O) {
    const float* z = buf_sel(which);
    int gt = blockIdx.x * 256 + threadIdx.x;
    int stride = gridDim.x * 256;
    float s = 0.f, q = 0.f;
    for (int i = gt; i < total; i += stride) { float v = z[i]; s += v; q += v * v; }
    __shared__ float bs[256], bq[256];
    bs[threadIdx.x] = s; bq[threadIdx.x] = q;
    __syncthreads();
    if (threadIdx.x < O) {
        for (int j = threadIdx.x + O; j < 256; j += O) { s += bs[j]; q += bq[j]; }
        atomicAdd(&g_sum[threadIdx.x], s);
        atomicAdd(&g_sumsq[threadIdx.x], q);
    }
}

__global__ void finalize_stats(const float* __restrict__ g, const float* __restrict__ bias, float invR) {
    int o = threadIdx.x;
    float m = g_sum[o] * invR;
    float v = g_sumsq[o] * invR - m * m;
    float rstd = rsqrtf(v + EPSF);
    float sc = g[o] * rstd;
    g_scale[o] = sc;
    g_shift[o] = bias[o] - m * sc;
}

// ---------------- FPS (matches jax scan: emit far, update dist, argmax) ----------------
template <int NPTS, int NSAMP, int TPB, int STAGE>
__global__ void fps_kernel() {
    constexpr int PPT = NPTS / TPB;
    const float* cx = (STAGE == 0) ? g_cx : g_c2x;
    const float* cy = (STAGE == 0) ? g_cy : g_c2y;
    const float* cz = (STAGE == 0) ? g_cz : g_c2z;
    int* fidx = (STAGE == 0) ? g_fidx1 : g_fidx2;
    int b = blockIdx.x, tid = threadIdx.x;
    const float* bx = cx + b * NPTS;
    const float* by = cy + b * NPTS;
    const float* bz = cz + b * NPTS;
    float px[PPT], py[PPT], pz[PPT], dist[PPT];
#pragma unroll
    for (int t = 0; t < PPT; t++) {
        int n = tid + t * TPB;
        px[t] = bx[n]; py[t] = by[n]; pz[t] = bz[n];
        dist[t] = 1e10f;
    }
    __shared__ float wv[TPB / 32];
    __shared__ int wi[TPB / 32];
    __shared__ int s_far;
    int far = 0;
    for (int s = 0; s < NSAMP; s++) {
        if (tid == 0) fidx[b * NSAMP + s] = far;
        float fx = bx[far], fy = by[far], fz = bz[far];
        float bv = -1.0f; int bi = 0x7fffffff;
#pragma unroll
        for (int t = 0; t < PPT; t++) {
            float dx = __fsub_rn(px[t], fx);
            float dy = __fsub_rn(py[t], fy);
            float dz = __fsub_rn(pz[t], fz);
            float d = __fadd_rn(__fadd_rn(__fmul_rn(dx, dx), __fmul_rn(dy, dy)), __fmul_rn(dz, dz));
            float nd = fminf(dist[t], d);
            dist[t] = nd;
            int n = tid + t * TPB;
            if (nd > bv) { bv = nd; bi = n; }
        }
#pragma unroll
        for (int off = 16; off > 0; off >>= 1) {
            float ov = __shfl_down_sync(0xffffffffu, bv, off);
            int oi = __shfl_down_sync(0xffffffffu, bi, off);
            if (ov > bv || (ov == bv && oi < bi)) { bv = ov; bi = oi; }
        }
        if ((tid & 31) == 0) { wv[tid >> 5] = bv; wi[tid >> 5] = bi; }
        __syncthreads();
        if (tid < 32) {
            constexpr int NW = TPB / 32;
            float v2 = (tid < NW) ? wv[tid] : -2.0f;
            int i2 = (tid < NW) ? wi[tid] : 0x7fffffff;
#pragma unroll
            for (int off = 16; off > 0; off >>= 1) {
                float ov = __shfl_down_sync(0xffffffffu, v2, off);
                int oi = __shfl_down_sync(0xffffffffu, i2, off);
                if (ov > v2 || (ov == v2 && oi < i2)) { v2 = ov; i2 = oi; }
            }
            if (tid == 0) s_far = i2;
        }
        __syncthreads();
        far = s_far;
    }
}

// ---------------- gather coords of sg1 sampled points ----------------
__global__ void gather_c2() {
    int i = blockIdx.x * 256 + threadIdx.x;   // BB*S1V
    int b = i >> 9;
    int id = g_fidx1[i];
    g_c2x[i] = g_cx[b * NN + id];
    g_c2y[i] = g_cy[b * NN + id];
    g_c2z[i] = g_cz[b * NN + id];
}

// ---------------- KNN: warp-resident top-32, replace-max insertion ----------------
template <int NPTS, int S, int STAGE>
__global__ void knn_kernel() {
    const float* cx = (STAGE == 0) ? g_cx : g_c2x;
    const float* cy = (STAGE == 0) ? g_cy : g_c2y;
    const float* cz = (STAGE == 0) ? g_cz : g_c2z;
    const int* fidx = (STAGE == 0) ? g_fidx1 : g_fidx2;
    int* knn = (STAGE == 0) ? g_knn1 : g_knn2;

    int gw = (blockIdx.x * blockDim.x + threadIdx.x) >> 5;   // global warp = centroid
    int lane = threadIdx.x & 31;
    int b = gw / S;
    const float* bx = cx + b * NPTS;
    const float* by = cy + b * NPTS;
    const float* bz = cz + b * NPTS;
    int ci = fidx[gw];
    float fx = bx[ci], fy = by[ci], fz = bz[ci];
    float fn = (fx * fx + fy * fy) + fz * fz;

    auto distf = [&](int n) {
        float xx = bx[n], yy = by[n], zz = bz[n];
        float nb = (xx * xx + yy * yy) + zz * zz;
        return fn + nb - 2.0f * (fx * xx + fy * yy + fz * zz);
    };

    float bd = distf(lane);
    int bidx = lane;

    float kv; int kl;
    {
        kv = bd; kl = lane;
#pragma unroll
        for (int off = 16; off > 0; off >>= 1) {
            float ov = __shfl_xor_sync(0xffffffffu, kv, off);
            int ol = __shfl_xor_sync(0xffffffffu, kl, off);
            if (ov > kv || (ov == kv && ol < kl)) { kv = ov; kl = ol; }
        }
    }
    for (int base = 32; base < NPTS; base += 32) {
        int n = base + lane;
        float d = distf(n);
        unsigned m = __ballot_sync(0xffffffffu, d < kv);
        while (m) {
            int src = __ffs(m) - 1;
            m &= m - 1;
            float dc = __shfl_sync(0xffffffffu, d, src);
            int nc = __shfl_sync(0xffffffffu, n, src);
            if (dc < kv) {
                if (lane == kl) { bd = dc; bidx = nc; }
                kv = bd; kl = lane;
#pragma unroll
                for (int off = 16; off > 0; off >>= 1) {
                    float ov = __shfl_xor_sync(0xffffffffu, kv, off);
                    int ol = __shfl_xor_sync(0xffffffffu, kl, off);
                    if (ov > kv || (ov == kv && ol < kl)) { kv = ov; kl = ol; }
                }
            }
        }
    }
    knn[gw * KV + lane] = bidx;
}

// ---------------- swizzled, double-buffered SGEMM: C[r,o] = sum_c A[r,c]*W[o,c] ----------------
// BNA: apply relu(a*g_scale[c]+g_shift[c]) to A elements on load.
__device__ __forceinline__ int swz(int col) {
    int blk = col >> 5;
    return (blk << 5) + (((col & 31) + (blk << 2)) & 31);
}

template <int CIN, int WS, bool BNA>
__global__ __launch_bounds__(256) void gemm_k(int asel, const float* __restrict__ Wp_in,
                                              int wsel, int csel, int O) {
    const float* A = buf_sel(asel);
    const float* W = Wp_in ? Wp_in : buf_sel(wsel);
    float* C = buf_sel(csel);
    __shared__ float As[2][8 * 132];
    __shared__ float Bs[2][8 * 132];
    int tid = threadIdx.x;
    int brow = blockIdx.x * 128, bcol = blockIdx.y * 128;
    int tx = tid & 15, ty = tid >> 4;
    int lr = tid >> 1, lc = (tid & 1) * 4;
    const float* Ap = A + (size_t)(brow + lr) * CIN + lc;
    const float* Wp = W + (size_t)(bcol + lr) * WS + lc;
    int wp = swz(lr);
    int sa0 = swz(ty * 8), sa1 = swz(ty * 8 + 4);
    int sb0 = swz(tx * 8), sb1 = swz(tx * 8 + 4);

    // panel 0
    float4 av = *(const float4*)Ap;
    float4 wv = *(const float4*)Wp;
    if (BNA) {
        float4 sc = *(const float4*)&g_scale[lc];
        float4 sh = *(const float4*)&g_shift[lc];
        av.x = fmaxf(av.x * sc.x + sh.x, 0.f);
        av.y = fmaxf(av.y * sc.y + sh.y, 0.f);
        av.z = fmaxf(av.z * sc.z + sh.z, 0.f);
        av.w = fmaxf(av.w * sc.w + sh.w, 0.f);
    }
    As[0][(lc + 0) * 132 + wp] = av.x; As[0][(lc + 1) * 132 + wp] = av.y;
    As[0][(lc + 2) * 132 + wp] = av.z; As[0][(lc + 3) * 132 + wp] = av.w;
    Bs[0][(lc + 0) * 132 + wp] = wv.x; Bs[0][(lc + 1) * 132 + wp] = wv.y;
    Bs[0][(lc + 2) * 132 + wp] = wv.z; Bs[0][(lc + 3) * 132 + wp] = wv.w;
    __syncthreads();

    float acc[8][8];
#pragma unroll
    for (int i = 0; i < 8; i++)
#pragma unroll
        for (int j = 0; j < 8; j++) acc[i][j] = 0.f;

    constexpr int NIT = CIN / 8;
#pragma unroll 2
    for (int it = 0; it < NIT; it++) {
        int cur = it & 1;
        float4 av2, wv2;
        if (it + 1 < NIT) {
            av2 = *(const float4*)(Ap + (it + 1) * 8);
            wv2 = *(const float4*)(Wp + (it + 1) * 8);
            if (BNA) {
                float4 sc = *(const float4*)&g_scale[(it + 1) * 8 + lc];
                float4 sh = *(const float4*)&g_shift[(it + 1) * 8 + lc];
                av2.x = fmaxf(av2.x * sc.x + sh.x, 0.f);
                av2.y = fmaxf(av2.y * sc.y + sh.y, 0.f);
                av2.z = fmaxf(av2.z * sc.z + sh.z, 0.f);
                av2.w = fmaxf(av2.w * sc.w + sh.w, 0.f);
            }
        }
#pragma unroll
        for (int k = 0; k < 8; k++) {
            float4 a0 = *(const float4*)&As[cur][k * 132 + sa0];
            float4 a1 = *(const float4*)&As[cur][k * 132 + sa1];
            float4 b0 = *(const float4*)&Bs[cur][k * 132 + sb0];
            float4 b1 = *(const float4*)&Bs[cur][k * 132 + sb1];
            float a[8] = {a0.x, a0.y, a0.z, a0.w, a1.x, a1.y, a1.z, a1.w};
            float bb[8] = {b0.x, b0.y, b0.z, b0.w, b1.x, b1.y, b1.z, b1.w};
#pragma unroll
            for (int i = 0; i < 8; i++)
#pragma unroll
                for (int j = 0; j < 8; j++) acc[i][j] += a[i] * bb[j];
        }
        if (it + 1 < NIT) {
            int nxt = 1 - cur;
            As[nxt][(lc + 0) * 132 + wp] = av2.x; As[nxt][(lc + 1) * 132 + wp] = av2.y;
            As[nxt][(lc + 2) * 132 + wp] = av2.z; As[nxt][(lc + 3) * 132 + wp] = av2.w;
            Bs[nxt][(lc + 0) * 132 + wp] = wv2.x; Bs[nxt][(lc + 1) * 132 + wp] = wv2.y;
            Bs[nxt][(lc + 2) * 132 + wp] = wv2.z; Bs[nxt][(lc + 3) * 132 + wp] = wv2.w;
            __syncthreads();
        }
    }
#pragma unroll
    for (int i = 0; i < 8; i++) {
        int r = brow + ty * 8 + i;
        float4* cp = (float4*)(C + (size_t)r * O + bcol + tx * 8);
        cp[0] = make_float4(acc[i][0], acc[i][1], acc[i][2], acc[i][3]);
        cp[1] = make_float4(acc[i][4], acc[i][5], acc[i][6], acc[i][7]);
    }
}

// ---------------- weight diffs: wdiff[o,d] = w[o, D+d] - w[o, d] ----------------
__global__ void wdiff1_k(const float* __restrict__ w) {
    int i = blockIdx.x * 256 + threadIdx.x;   // 128*64
    int o = i >> 6, d = i & 63;
    g_wdiff1[i] = w[o * 128 + 64 + d] - w[o * 128 + d];
}
__global__ void wdiff2_k(const float* __restrict__ w) {
    int i = blockIdx.x * 256 + threadIdx.x;   // 256*128
    int o = i >> 7, d = i & 127;
    g_wdiff2[i] = w[o * 256 + 128 + d] - w[o * 256 + d];
}

// ---------------- center feature gathers ----------------
__global__ void gather_cfeat1() {     // bn-relu applied (scale/shift = cbr2 stats)
    int i = blockIdx.x * 256 + threadIdx.x;   // 8192*64
    int r = i >> 6, c = i & 63;
    int b = r >> 9;
    int fid = g_fidx1[r];
    float v = g_f[((size_t)(b * NN + fid)) * 64 + c];
    g_cfeat1[i] = fmaxf(v * g_scale[c] + g_shift[c], 0.f);
}
__global__ void gather_cfeat2() {     // f1 already final
    int i = blockIdx.x * 256 + threadIdx.x;   // 4096*128
    int r = i >> 7, c = i & 127;
    int b = r >> 8;
    int fid = g_fidx2[r];
    g_cfeat2[i] = g_f1[((size_t)(b * S1V + fid)) * 128 + c];
}

// ---------------- assemble layer-1 outputs: y[row,o] = G[nb,o] + Cc[bs,o] ----------------
__global__ void assemble1() {
    int idx = blockIdx.x * 256 + threadIdx.x;   // 262144 rows * 32 float4
    int row = idx >> 5, c4 = (idx & 31) * 4;
    int bs = row >> 5;
    int b = bs >> 9;
    int nb = g_knn1[row];
    float4 g = *(const float4*)&g_zbuf[((size_t)(b * NN + nb)) * 128 + c4];
    float4 cc = *(const float4*)&g_c1out[(size_t)bs * 128 + c4];
    float4 r = make_float4(g.x + cc.x, g.y + cc.y, g.z + cc.z, g.w + cc.w);
    *(float4*)&g_abuf[(size_t)row * 128 + c4] = r;
}
__global__ void assemble2() {
    int idx = blockIdx.x * 256 + threadIdx.x;   // 131072 rows * 64 float4
    int row = idx >> 6, c4 = (idx & 63) * 4;
    int bs = row >> 5;
    int b = bs >> 8;
    int nb = g_knn2[row];
    float4 g = *(const float4*)&g_zbuf[((size_t)(b * S1V + nb)) * 256 + c4];
    float4 cc = *(const float4*)&g_c2out[(size_t)bs * 256 + c4];
    float4 r = make_float4(g.x + cc.x, g.y + cc.y, g.z + cc.z, g.w + cc.w);
    *(float4*)&g_abuf[(size_t)row * 256 + c4] = r;
}

// ---------------- max-pool over K with fused BN-ReLU ----------------
__global__ void maxpool1() {
    int bs = blockIdx.x;             // BB*S1V
    int o = threadIdx.x;             // 128
    const float* base = g_zbuf + (size_t)bs * KV * 128;
    float sc = g_scale[o], sh = g_shift[o];
    float m = -1e30f;
#pragma unroll
    for (int k = 0; k < KV; k++) {
        float v = fmaxf(base[k * 128 + o] * sc + sh, 0.f);
        m = fmaxf(m, v);
    }
    g_f1[bs * 128 + o] = m;
}

__global__ void maxpool2(float* __restrict__ out) {
    int bs = blockIdx.x;             // BB*S2V
    int o = threadIdx.x;             // 256
    int b = bs >> 8, s = bs & 255;
    const float* base = g_zbuf + (size_t)bs * KV * 256;
    float sc = g_scale[o], sh = g_shift[o];
    float m = -1e30f;
#pragma unroll
    for (int k = 0; k < KV; k++) {
        float v = fmaxf(base[k * 256 + o] * sc + sh, 0.f);
        m = fmaxf(m, v);
    }
    out[((size_t)b * 256 + o) * 256 + s] = m;
}

// ---------------- launch sequence ----------------
extern "C" void kernel_launch(void* const* d_in, const int* in_sizes, int n_in,
                              void* d_out, int out_size) {
    const float* x     = (const float*)d_in[0];
    const float* w1    = (const float*)d_in[1];
    const float* w2    = (const float*)d_in[2];
    const float* g1    = (const float*)d_in[3];
    const float* b1    = (const float*)d_in[4];
    const float* g2    = (const float*)d_in[5];
    const float* b2    = (const float*)d_in[6];
    const float* s1w1  = (const float*)d_in[7];
    const float* s1w2  = (const float*)d_in[8];
    const float* s1g1  = (const float*)d_in[9];
    const float* s1b1  = (const float*)d_in[10];
    const float* s1g2  = (const float*)d_in[11];
    const float* s1b2  = (const float*)d_in[12];
    const float* s2w1  = (const float*)d_in[13];
    const float* s2w2  = (const float*)d_in[14];
    const float* s2g1  = (const float*)d_in[15];
    const float* s2b1  = (const float*)d_in[16];
    const float* s2g2  = (const float*)d_in[17];
    const float* s2b2  = (const float*)d_in[18];
    float* out = (float*)d_out;

    const int RP = BB * NN;                 // 65536
    const int R1 = BB * S1V * KV;           // 262144
    const int R2 = BB * S2V * KV;           // 131072

    prep_coords<<<RP / 256, 256>>>(x);

    // point_cbr 1 (raw) + stats
    cbr1_kernel<<<RP * 64 / 256, 256>>>(x, w1);
    zero_stats<<<1, 256>>>();
    stats_kernel<<<512, 256>>>(0, RP * 64, 64);
    finalize_stats<<<1, 64>>>(g1, b1, 1.0f / RP);

    // point_cbr 2 (bn-relu fused on load) -> g_f raw, + stats
    cbr2_kernel<<<RP / 4, 256>>>(w2);
    zero_stats<<<1, 256>>>();
    stats_kernel<<<512, 256>>>(2, RP * 64, 64);
    finalize_stats<<<1, 64>>>(g2, b2, 1.0f / RP);

    // sg1 sampling / knn (independent of features)
    fps_kernel<NN, S1V, 1024, 0><<<BB, 1024>>>();
    gather_c2<<<BB * S1V / 256, 256>>>();
    knn_kernel<NN, S1V, 0><<<BB * S1V / 4, 128>>>();

    // factored sg1 layer 1:
    // G1 = bnrelu(f) @ w1a^T  (per point)          -> zbuf [65536 x 128]
    gemm_k<64, 128, true><<<dim3(512, 1), 256>>>(2, s1w1, -1, 0, 128);
    // center feats + C1 = cfeat1 @ wdiff1^T        -> c1out [8192 x 128]
    gather_cfeat1<<<BB * S1V * 64 / 256, 256>>>();
    wdiff1_k<<<128 * 64 / 256, 256>>>(s1w1);
    gemm_k<64, 64, false><<<dim3(64, 1), 256>>>(3, nullptr, 7, 5, 128);
    // y1 = G1[nb] + C1[center]                     -> abuf [262144 x 128]
    assemble1<<<R1 * 32 / 256, 256>>>();
    zero_stats<<<1, 256>>>();
    stats_kernel<<<512, 256>>>(1, R1 * 128, 128);
    finalize_stats<<<1, 128>>>(s1g1, s1b1, 1.0f / R1);

    // sg1 layer 2: bnrelu(y1) @ s1w2^T             -> zbuf [262144 x 128]
    gemm_k<128, 128, true><<<dim3(2048, 1), 256>>>(1, s1w2, -1, 0, 128);
    zero_stats<<<1, 256>>>();
    stats_kernel<<<512, 256>>>(0, R1 * 128, 128);
    finalize_stats<<<1, 128>>>(s1g2, s1b2, 1.0f / R1);

    // maxpool over K with fused bn-relu            -> g_f1 [8192 x 128]
    maxpool1<<<BB * S1V, 128>>>();

    // sg2 sampling / knn
    fps_kernel<S1V, S2V, 512, 1><<<BB, 512>>>();
    knn_kernel<S1V, S2V, 1><<<BB * S2V / 4, 128>>>();

    // factored sg2 layer 1:
    // G2 = f1 @ w2a^T                              -> zbuf [8192 x 256]
    gemm_k<128, 256, false><<<dim3(64, 2), 256>>>(9, s2w1, -1, 0, 256);
    gather_cfeat2<<<BB * S2V * 128 / 256, 256>>>();
    wdiff2_k<<<256 * 128 / 256, 256>>>(s2w1);
    // C2 = cfeat2 @ wdiff2^T                       -> c2out [4096 x 256]
    gemm_k<128, 128, false><<<dim3(32, 2), 256>>>(4, nullptr, 8, 6, 256);
    // y2 = G2[nb] + C2[center]                     -> abuf [131072 x 256]
    assemble2<<<R2 * 64 / 256, 256>>>();
    zero_stats<<<1, 256>>>();
    stats_kernel<<<512, 256>>>(1, R2 * 256, 256);
    finalize_stats<<<1, 256>>>(s2g1, s2b1, 1.0f / R2);

    // sg2 layer 2: bnrelu(y2) @ s2w2^T             -> zbuf [131072 x 256]
    gemm_k<256, 256, true><<<dim3(1024, 2), 256>>>(1, s2w2, -1, 0, 256);
    zero_stats<<<1, 256>>>();
    stats_kernel<<<512, 256>>>(0, R2 * 256, 256);
    finalize_stats<<<1, 256>>>(s2g2, s2b2, 1.0f / R2);

    // final maxpool + bn-relu -> out (B, 256, S2)
    maxpool2<<<BB * S2V, 256>>>(out);
}

// round 12
// speedup vs baseline: 1.6655x; 1.2106x over previous
#include <cuda_runtime.h>

#define BB 16
#define NN 4096
#define S1V 512
#define S2V 256
#define KV 32
#define EPSF 1e-5f

// ---------------- scratch (static device globals; no allocation) ----------------
__device__ __align__(16) float g_zbuf[33554432];            // ping (G1 / G2 live here)
__device__ __align__(16) float g_f[BB * NN * 64];           // raw cbr2 output (B,N,64)
__device__ __align__(16) float g_f1[BB * S1V * 128];        // sg1 final features (B,S1,128)
__device__ __align__(16) float g_cfeat1[BB * S1V * 64];     // bn-relu'd center feats sg1
__device__ __align__(16) float g_cfeat2[BB * S2V * 128];    // center feats sg2
__device__ __align__(16) float g_c1out[BB * S1V * 128];     // center @ wdiff1^T
__device__ __align__(16) float g_c2out[BB * S2V * 256];     // center @ wdiff2^T
__device__ __align__(16) float g_wdiff1[128 * 64];
__device__ __align__(16) float g_wdiff2[256 * 128];
__device__ __align__(16) float g_pmax[1048576];             // per-center raw max
__device__ __align__(16) float g_pmin[1048576];             // per-center raw min
__device__ float g_cx[BB * NN], g_cy[BB * NN], g_cz[BB * NN];
__device__ float g_c2x[BB * S1V], g_c2y[BB * S1V], g_c2z[BB * S1V];
__device__ int   g_fidx1[BB * S1V], g_fidx2[BB * S2V];
__device__ int   g_knn1[BB * S1V * KV], g_knn2[BB * S2V * KV];
__device__ __align__(16) float g_sum[256], g_sumsq[256];
__device__ __align__(16) float g_scale[256], g_shift[256];

__device__ __forceinline__ float* buf_sel(int w) {
    switch (w) {
        case 0: return g_zbuf;
        case 2: return g_f;
        case 3: return g_cfeat1;
        case 4: return g_cfeat2;
        case 5: return g_c1out;
        case 6: return g_c2out;
        case 7: return g_wdiff1;
        case 8: return g_wdiff2;
        case 9: return g_f1;
    }
    return g_zbuf;
}

// ---------------- coords prep ----------------
__global__ void prep_coords(const float* __restrict__ x) {
    int i = blockIdx.x * 256 + threadIdx.x;
    int b = i >> 12, n = i & 4095;
    const float* xb = x + (size_t)b * 3 * NN;
    g_cx[i] = xb[n];
    g_cy[i] = xb[NN + n];
    g_cz[i] = xb[2 * NN + n];
}

// ---------------- point_cbr stage 1 (raw) ----------------
__global__ void cbr1_kernel(const float* __restrict__ x, const float* __restrict__ w1) {
    int idx = blockIdx.x * 256 + threadIdx.x;
    int r = idx >> 6, o = idx & 63;
    int b = r >> 12, n = r & 4095;
    const float* xb = x + (size_t)b * 3 * NN;
    float v = w1[o * 3 + 0] * xb[n] + w1[o * 3 + 1] * xb[NN + n] + w1[o * 3 + 2] * xb[2 * NN + n];
    g_zbuf[idx] = v;
}

// ---------------- point_cbr stage 2: bnrelu(zbuf) @ w2^T -> g_f (raw) ----------------
__global__ void cbr2_kernel(const float* __restrict__ w2) {
    __shared__ float ys[4][64];
    __shared__ float wst[64 * 64];
    int tid = threadIdx.x;
    int r0 = blockIdx.x * 4;
    for (int j = tid; j < 4096; j += 256) {
        int o = j >> 6, c = j & 63;
        wst[c * 64 + o] = w2[j];
    }
    {
        int c = tid & 63;
        float v = g_zbuf[r0 * 64 + tid];
        v = fmaxf(v * g_scale[c] + g_shift[c], 0.f);
        ((float*)ys)[tid] = v;
    }
    __syncthreads();
    int rl = tid >> 6, o = tid & 63;
    float acc = 0.f;
#pragma unroll 16
    for (int c = 0; c < 64; c++) acc += ys[rl][c] * wst[c * 64 + o];
    g_f[(r0 + rl) * 64 + o] = acc;
}

// ---------------- BN stats / finalize ----------------
__global__ void zero_stats() { g_sum[threadIdx.x] = 0.f; g_sumsq[threadIdx.x] = 0.f; }

__global__ void stats_kernel(int which, int total, int O) {
    const float* z = buf_sel(which);
    int gt = blockIdx.x * 256 + threadIdx.x;
    int stride = gridDim.x * 256;
    float s = 0.f, q = 0.f;
    for (int i = gt; i < total; i += stride) { float v = z[i]; s += v; q += v * v; }
    __shared__ float bs[256], bq[256];
    bs[threadIdx.x] = s; bq[threadIdx.x] = q;
    __syncthreads();
    if (threadIdx.x < O) {
        for (int j = threadIdx.x + O; j < 256; j += O) { s += bs[j]; q += bq[j]; }
        atomicAdd(&g_sum[threadIdx.x], s);
        atomicAdd(&g_sumsq[threadIdx.x], q);
    }
}

__global__ void finalize_stats(const float* __restrict__ g, const float* __restrict__ bias, float invR) {
    int o = threadIdx.x;
    float m = g_sum[o] * invR;
    float v = g_sumsq[o] * invR - m * m;
    float rstd = rsqrtf(v + EPSF);
    float sc = g[o] * rstd;
    g_scale[o] = sc;
    g_shift[o] = bias[o] - m * sc;
}

// ---------------- FPS (bit-exact vs jax scan) ----------------
template <int NPTS, int NSAMP, int TPB, int STAGE>
__global__ void fps_kernel() {
    constexpr int PPT = NPTS / TPB;
    const float* cx = (STAGE == 0) ? g_cx : g_c2x;
    const float* cy = (STAGE == 0) ? g_cy : g_c2y;
    const float* cz = (STAGE == 0) ? g_cz : g_c2z;
    int* fidx = (STAGE == 0) ? g_fidx1 : g_fidx2;
    int b = blockIdx.x, tid = threadIdx.x;
    const float* bx = cx + b * NPTS;
    const float* by = cy + b * NPTS;
    const float* bz = cz + b * NPTS;
    float px[PPT], py[PPT], pz[PPT], dist[PPT];
#pragma unroll
    for (int t = 0; t < PPT; t++) {
        int n = tid + t * TPB;
        px[t] = bx[n]; py[t] = by[n]; pz[t] = bz[n];
        dist[t] = 1e10f;
    }
    __shared__ float wv[TPB / 32];
    __shared__ int wi[TPB / 32];
    __shared__ int s_far;
    int far = 0;
    for (int s = 0; s < NSAMP; s++) {
        if (tid == 0) fidx[b * NSAMP + s] = far;
        float fx = bx[far], fy = by[far], fz = bz[far];
        float bv = -1.0f; int bi = 0x7fffffff;
#pragma unroll
        for (int t = 0; t < PPT; t++) {
            float dx = __fsub_rn(px[t], fx);
            float dy = __fsub_rn(py[t], fy);
            float dz = __fsub_rn(pz[t], fz);
            float d = __fadd_rn(__fadd_rn(__fmul_rn(dx, dx), __fmul_rn(dy, dy)), __fmul_rn(dz, dz));
            float nd = fminf(dist[t], d);
            dist[t] = nd;
            int n = tid + t * TPB;
            if (nd > bv) { bv = nd; bi = n; }
        }
#pragma unroll
        for (int off = 16; off > 0; off >>= 1) {
            float ov = __shfl_down_sync(0xffffffffu, bv, off);
            int oi = __shfl_down_sync(0xffffffffu, bi, off);
            if (ov > bv || (ov == bv && oi < bi)) { bv = ov; bi = oi; }
        }
        if ((tid & 31) == 0) { wv[tid >> 5] = bv; wi[tid >> 5] = bi; }
        __syncthreads();
        if (tid < 32) {
            constexpr int NW = TPB / 32;
            float v2 = (tid < NW) ? wv[tid] : -2.0f;
            int i2 = (tid < NW) ? wi[tid] : 0x7fffffff;
#pragma unroll
            for (int off = 16; off > 0; off >>= 1) {
                float ov = __shfl_down_sync(0xffffffffu, v2, off);
                int oi = __shfl_down_sync(0xffffffffu, i2, off);
                if (ov > v2 || (ov == v2 && oi < i2)) { v2 = ov; i2 = oi; }
            }
            if (tid == 0) s_far = i2;
        }
        __syncthreads();
        far = s_far;
    }
}

// ---------------- gather coords of sg1 sampled points ----------------
__global__ void gather_c2() {
    int i = blockIdx.x * 256 + threadIdx.x;
    int b = i >> 9;
    int id = g_fidx1[i];
    g_c2x[i] = g_cx[b * NN + id];
    g_c2y[i] = g_cy[b * NN + id];
    g_c2z[i] = g_cz[b * NN + id];
}

// ---------------- KNN: warp-resident top-32 ----------------
template <int NPTS, int S, int STAGE>
__global__ void knn_kernel() {
    const float* cx = (STAGE == 0) ? g_cx : g_c2x;
    const float* cy = (STAGE == 0) ? g_cy : g_c2y;
    const float* cz = (STAGE == 0) ? g_cz : g_c2z;
    const int* fidx = (STAGE == 0) ? g_fidx1 : g_fidx2;
    int* knn = (STAGE == 0) ? g_knn1 : g_knn2;

    int gw = (blockIdx.x * blockDim.x + threadIdx.x) >> 5;
    int lane = threadIdx.x & 31;
    int b = gw / S;
    const float* bx = cx + b * NPTS;
    const float* by = cy + b * NPTS;
    const float* bz = cz + b * NPTS;
    int ci = fidx[gw];
    float fx = bx[ci], fy = by[ci], fz = bz[ci];
    float fn = (fx * fx + fy * fy) + fz * fz;

    auto distf = [&](int n) {
        float xx = bx[n], yy = by[n], zz = bz[n];
        float nb = (xx * xx + yy * yy) + zz * zz;
        return fn + nb - 2.0f * (fx * xx + fy * yy + fz * zz);
    };

    float bd = distf(lane);
    int bidx = lane;

    float kv; int kl;
    {
        kv = bd; kl = lane;
#pragma unroll
        for (int off = 16; off > 0; off >>= 1) {
            float ov = __shfl_xor_sync(0xffffffffu, kv, off);
            int ol = __shfl_xor_sync(0xffffffffu, kl, off);
            if (ov > kv || (ov == kv && ol < kl)) { kv = ov; kl = ol; }
        }
    }
    for (int base = 32; base < NPTS; base += 32) {
        int n = base + lane;
        float d = distf(n);
        unsigned m = __ballot_sync(0xffffffffu, d < kv);
        while (m) {
            int src = __ffs(m) - 1;
            m &= m - 1;
            float dc = __shfl_sync(0xffffffffu, d, src);
            int nc = __shfl_sync(0xffffffffu, n, src);
            if (dc < kv) {
                if (lane == kl) { bd = dc; bidx = nc; }
                kv = bd; kl = lane;
#pragma unroll
                for (int off = 16; off > 0; off >>= 1) {
                    float ov = __shfl_xor_sync(0xffffffffu, kv, off);
                    int ol = __shfl_xor_sync(0xffffffffu, kl, off);
                    if (ov > kv || (ov == kv && ol < kl)) { kv = ov; kl = ol; }
                }
            }
        }
    }
    knn[gw * KV + lane] = bidx;
}

// ---------------- smem swizzle ----------------
__device__ __forceinline__ int swz(int col) {
    int blk = col >> 5;
    return (blk << 5) + (((col & 31) + (blk << 2)) & 31);
}

// ---------------- plain swizzled double-buffered SGEMM (small GEMMs) ----------------
template <int CIN, int WS, bool BNA>
__global__ __launch_bounds__(256) void gemm_k(int asel, const float* __restrict__ Wp_in,
                                              int wsel, int csel, int O) {
    const float* A = buf_sel(asel);
    const float* W = Wp_in ? Wp_in : buf_sel(wsel);
    float* C = buf_sel(csel);
    __shared__ float As[2][8 * 132];
    __shared__ float Bs[2][8 * 132];
    int tid = threadIdx.x;
    int brow = blockIdx.x * 128, bcol = blockIdx.y * 128;
    int tx = tid & 15, ty = tid >> 4;
    int lr = tid >> 1, lc = (tid & 1) * 4;
    const float* Ap = A + (size_t)(brow + lr) * CIN + lc;
    const float* Wp = W + (size_t)(bcol + lr) * WS + lc;
    int wp = swz(lr);
    int sa0 = swz(ty * 8), sa1 = swz(ty * 8 + 4);
    int sb0 = swz(tx * 8), sb1 = swz(tx * 8 + 4);

    float4 av = *(const float4*)Ap;
    float4 wv = *(const float4*)Wp;
    if (BNA) {
        float4 sc = *(const float4*)&g_scale[lc];
        float4 sh = *(const float4*)&g_shift[lc];
        av.x = fmaxf(av.x * sc.x + sh.x, 0.f);
        av.y = fmaxf(av.y * sc.y + sh.y, 0.f);
        av.z = fmaxf(av.z * sc.z + sh.z, 0.f);
        av.w = fmaxf(av.w * sc.w + sh.w, 0.f);
    }
    As[0][(lc + 0) * 132 + wp] = av.x; As[0][(lc + 1) * 132 + wp] = av.y;
    As[0][(lc + 2) * 132 + wp] = av.z; As[0][(lc + 3) * 132 + wp] = av.w;
    Bs[0][(lc + 0) * 132 + wp] = wv.x; Bs[0][(lc + 1) * 132 + wp] = wv.y;
    Bs[0][(lc + 2) * 132 + wp] = wv.z; Bs[0][(lc + 3) * 132 + wp] = wv.w;
    __syncthreads();

    float acc[8][8];
#pragma unroll
    for (int i = 0; i < 8; i++)
#pragma unroll
        for (int j = 0; j < 8; j++) acc[i][j] = 0.f;

    constexpr int NIT = CIN / 8;
#pragma unroll 2
    for (int it = 0; it < NIT; it++) {
        int cur = it & 1;
        float4 av2, wv2;
        if (it + 1 < NIT) {
            av2 = *(const float4*)(Ap + (it + 1) * 8);
            wv2 = *(const float4*)(Wp + (it + 1) * 8);
            if (BNA) {
                float4 sc = *(const float4*)&g_scale[(it + 1) * 8 + lc];
                float4 sh = *(const float4*)&g_shift[(it + 1) * 8 + lc];
                av2.x = fmaxf(av2.x * sc.x + sh.x, 0.f);
                av2.y = fmaxf(av2.y * sc.y + sh.y, 0.f);
                av2.z = fmaxf(av2.z * sc.z + sh.z, 0.f);
                av2.w = fmaxf(av2.w * sc.w + sh.w, 0.f);
            }
        }
#pragma unroll
        for (int k = 0; k < 8; k++) {
            float4 a0 = *(const float4*)&As[cur][k * 132 + sa0];
            float4 a1 = *(const float4*)&As[cur][k * 132 + sa1];
            float4 b0 = *(const float4*)&Bs[cur][k * 132 + sb0];
            float4 b1 = *(const float4*)&Bs[cur][k * 132 + sb1];
            float a[8] = {a0.x, a0.y, a0.z, a0.w, a1.x, a1.y, a1.z, a1.w};
            float bb[8] = {b0.x, b0.y, b0.z, b0.w, b1.x, b1.y, b1.z, b1.w};
#pragma unroll
            for (int i = 0; i < 8; i++)
#pragma unroll
                for (int j = 0; j < 8; j++) acc[i][j] += a[i] * bb[j];
        }
        if (it + 1 < NIT) {
            int nxt = 1 - cur;
            As[nxt][(lc + 0) * 132 + wp] = av2.x; As[nxt][(lc + 1) * 132 + wp] = av2.y;
            As[nxt][(lc + 2) * 132 + wp] = av2.z; As[nxt][(lc + 3) * 132 + wp] = av2.w;
            Bs[nxt][(lc + 0) * 132 + wp] = wv2.x; Bs[nxt][(lc + 1) * 132 + wp] = wv2.y;
            Bs[nxt][(lc + 2) * 132 + wp] = wv2.z; Bs[nxt][(lc + 3) * 132 + wp] = wv2.w;
            __syncthreads();
        }
    }
#pragma unroll
    for (int i = 0; i < 8; i++) {
        int r = brow + ty * 8 + i;
        float4* cp = (float4*)(C + (size_t)r * O + bcol + tx * 8);
        cp[0] = make_float4(acc[i][0], acc[i][1], acc[i][2], acc[i][3]);
        cp[1] = make_float4(acc[i][4], acc[i][5], acc[i][6], acc[i][7]);
    }
}

// ---------------- FUSED layer-2 GEMM: gather+add+BN-ReLU on A-load,
//                  epilogue = per-center max/min + per-col sum/sumsq (no C write) ----
template <int CIN, int STAGE>
__global__ __launch_bounds__(256) void gemm2_fused(const float* __restrict__ W) {
    const float* G = g_zbuf;
    const float* C = (STAGE == 0) ? g_c1out : g_c2out;
    const int* knn = (STAGE == 0) ? g_knn1 : g_knn2;
    constexpr int NPTS = (STAGE == 0) ? NN : S1V;
    constexpr int BSH = (STAGE == 0) ? 9 : 8;

    __shared__ float As[2][8 * 132];
    __shared__ float Bs[2][8 * 132];
    int tid = threadIdx.x;
    int brow = blockIdx.x * 128, bcol = blockIdx.y * 128;
    int tx = tid & 15, ty = tid >> 4;
    int lr = tid >> 1, lc = (tid & 1) * 4;

    int grow = brow + lr;
    int nb = knn[grow];
    int bs = grow >> 5;
    int b = bs >> BSH;
    const float* Gp = G + ((size_t)(b * NPTS + nb)) * CIN + lc;
    const float* Cp = C + (size_t)bs * CIN + lc;
    const float* Wp = W + (size_t)(bcol + lr) * CIN + lc;
    int wp = swz(lr);
    int sa0 = swz(ty * 8), sa1 = swz(ty * 8 + 4);
    int sb0 = swz(tx * 8), sb1 = swz(tx * 8 + 4);

    // panel 0
    {
        float4 gv = *(const float4*)Gp;
        float4 cv = *(const float4*)Cp;
        float4 wv = *(const float4*)Wp;
        float4 sc = *(const float4*)&g_scale[lc];
        float4 sh = *(const float4*)&g_shift[lc];
        float ax = fmaxf((gv.x + cv.x) * sc.x + sh.x, 0.f);
        float ay = fmaxf((gv.y + cv.y) * sc.y + sh.y, 0.f);
        float az = fmaxf((gv.z + cv.z) * sc.z + sh.z, 0.f);
        float aw = fmaxf((gv.w + cv.w) * sc.w + sh.w, 0.f);
        As[0][(lc + 0) * 132 + wp] = ax; As[0][(lc + 1) * 132 + wp] = ay;
        As[0][(lc + 2) * 132 + wp] = az; As[0][(lc + 3) * 132 + wp] = aw;
        Bs[0][(lc + 0) * 132 + wp] = wv.x; Bs[0][(lc + 1) * 132 + wp] = wv.y;
        Bs[0][(lc + 2) * 132 + wp] = wv.z; Bs[0][(lc + 3) * 132 + wp] = wv.w;
    }
    __syncthreads();

    float acc[8][8];
#pragma unroll
    for (int i = 0; i < 8; i++)
#pragma unroll
        for (int j = 0; j < 8; j++) acc[i][j] = 0.f;

    constexpr int NIT = CIN / 8;
#pragma unroll 2
    for (int it = 0; it < NIT; it++) {
        int cur = it & 1;
        float axp, ayp, azp, awp;
        float4 wv2;
        if (it + 1 < NIT) {
            float4 gv = *(const float4*)(Gp + (it + 1) * 8);
            float4 cv = *(const float4*)(Cp + (it + 1) * 8);
            wv2 = *(const float4*)(Wp + (it + 1) * 8);
            float4 sc = *(const float4*)&g_scale[(it + 1) * 8 + lc];
            float4 sh = *(const float4*)&g_shift[(it + 1) * 8 + lc];
            axp = fmaxf((gv.x + cv.x) * sc.x + sh.x, 0.f);
            ayp = fmaxf((gv.y + cv.y) * sc.y + sh.y, 0.f);
            azp = fmaxf((gv.z + cv.z) * sc.z + sh.z, 0.f);
            awp = fmaxf((gv.w + cv.w) * sc.w + sh.w, 0.f);
        }
#pragma unroll
        for (int k = 0; k < 8; k++) {
            float4 a0 = *(const float4*)&As[cur][k * 132 + sa0];
            float4 a1 = *(const float4*)&As[cur][k * 132 + sa1];
            float4 b0 = *(const float4*)&Bs[cur][k * 132 + sb0];
            float4 b1 = *(const float4*)&Bs[cur][k * 132 + sb1];
            float a[8] = {a0.x, a0.y, a0.z, a0.w, a1.x, a1.y, a1.z, a1.w};
            float bb[8] = {b0.x, b0.y, b0.z, b0.w, b1.x, b1.y, b1.z, b1.w};
#pragma unroll
            for (int i = 0; i < 8; i++)
#pragma unroll
                for (int j = 0; j < 8; j++) acc[i][j] += a[i] * bb[j];
        }
        if (it + 1 < NIT) {
            int nxt = 1 - cur;
            As[nxt][(lc + 0) * 132 + wp] = axp; As[nxt][(lc + 1) * 132 + wp] = ayp;
            As[nxt][(lc + 2) * 132 + wp] = azp; As[nxt][(lc + 3) * 132 + wp] = awp;
            Bs[nxt][(lc + 0) * 132 + wp] = wv2.x; Bs[nxt][(lc + 1) * 132 + wp] = wv2.y;
            Bs[nxt][(lc + 2) * 132 + wp] = wv2.z; Bs[nxt][(lc + 3) * 132 + wp] = wv2.w;
            __syncthreads();
        }
    }

    // ---- epilogue: per-thread partials over its 8 rows (one center: 8 | 32) ----
    float tmax[8], tmin[8], tsum[8], tsq[8];
#pragma unroll
    for (int j = 0; j < 8; j++) { tmax[j] = -1e30f; tmin[j] = 1e30f; tsum[j] = 0.f; tsq[j] = 0.f; }
#pragma unroll
    for (int i = 0; i < 8; i++)
#pragma unroll
        for (int j = 0; j < 8; j++) {
            float v = acc[i][j];
            tmax[j] = fmaxf(tmax[j], v);
            tmin[j] = fminf(tmin[j], v);
            tsum[j] += v;
            tsq[j] += v * v;
        }

    float* redA = &As[0][0];   // 2112 floats, used as [16][132]
    float* redB = &Bs[0][0];
    __syncthreads();
#pragma unroll
    for (int j = 0; j < 8; j++) {
        redA[ty * 132 + tx * 8 + j] = tmax[j];
        redB[ty * 132 + tx * 8 + j] = tmin[j];
    }
    __syncthreads();
    {
        int ct = tid >> 6;                  // center within block (0..3)
        int base = (tid & 63) * 2;
        int bs0 = brow >> 5;
#pragma unroll
        for (int u = 0; u < 2; u++) {
            int col = base + u;
            float m = -1e30f, mn = 1e30f;
#pragma unroll
            for (int v = 0; v < 4; v++) {
                m = fmaxf(m, redA[(ct * 4 + v) * 132 + col]);
                mn = fminf(mn, redB[(ct * 4 + v) * 132 + col]);
            }
            size_t o = (size_t)(bs0 + ct) * CIN + bcol + col;
            g_pmax[o] = m;
            g_pmin[o] = mn;
        }
    }
    __syncthreads();
#pragma unroll
    for (int j = 0; j < 8; j++) {
        redA[ty * 132 + tx * 8 + j] = tsum[j];
        redB[ty * 132 + tx * 8 + j] = tsq[j];
    }
    __syncthreads();
    if (tid < 128) {
        float s = 0.f;
#pragma unroll
        for (int v = 0; v < 16; v++) s += redA[v * 132 + tid];
        atomicAdd(&g_sum[bcol + tid], s);
    } else {
        int col = tid - 128;
        float s = 0.f;
#pragma unroll
        for (int v = 0; v < 16; v++) s += redB[v * 132 + col];
        atomicAdd(&g_sumsq[bcol + col], s);
    }
}

// ---------------- gather-stats for y = G[nb] + C[center] (no materialization) -------
template <int CIN, int STAGE>
__global__ void stats_gather_k(int R) {
    const float* G = g_zbuf;
    const float* C = (STAGE == 0) ? g_c1out : g_c2out;
    const int* knn = (STAGE == 0) ? g_knn1 : g_knn2;
    constexpr int NPTS = (STAGE == 0) ? NN : S1V;
    constexpr int BSH = (STAGE == 0) ? 9 : 8;
    constexpr int NSEG = CIN / 128;

    int wid = (blockIdx.x * blockDim.x + threadIdx.x) >> 5;
    int lane = threadIdx.x & 31;
    int nw = (gridDim.x * blockDim.x) >> 5;
    float s[NSEG][4], q[NSEG][4];
#pragma unroll
    for (int sg = 0; sg < NSEG; sg++)
#pragma unroll
        for (int j = 0; j < 4; j++) { s[sg][j] = 0.f; q[sg][j] = 0.f; }

    for (int row = wid; row < R; row += nw) {
        int nb = knn[row];
        int bs = row >> 5;
        int b = bs >> BSH;
        size_t gb = ((size_t)(b * NPTS + nb)) * CIN;
        size_t cb = (size_t)bs * CIN;
#pragma unroll
        for (int sg = 0; sg < NSEG; sg++) {
            int col = sg * 128 + lane * 4;
            float4 g = *(const float4*)(G + gb + col);
            float4 c = *(const float4*)(C + cb + col);
            float y0 = g.x + c.x, y1 = g.y + c.y, y2 = g.z + c.z, y3 = g.w + c.w;
            s[sg][0] += y0; s[sg][1] += y1; s[sg][2] += y2; s[sg][3] += y3;
            q[sg][0] += y0 * y0; q[sg][1] += y1 * y1; q[sg][2] += y2 * y2; q[sg][3] += y3 * y3;
        }
    }
    __shared__ float ss[CIN], sq[CIN];
    for (int t = threadIdx.x; t < CIN; t += 256) { ss[t] = 0.f; sq[t] = 0.f; }
    __syncthreads();
#pragma unroll
    for (int sg = 0; sg < NSEG; sg++)
#pragma unroll
        for (int j = 0; j < 4; j++) {
            atomicAdd(&ss[sg * 128 + lane * 4 + j], s[sg][j]);
            atomicAdd(&sq[sg * 128 + lane * 4 + j], q[sg][j]);
        }
    __syncthreads();
    for (int t = threadIdx.x; t < CIN; t += 256) {
        atomicAdd(&g_sum[t], ss[t]);
        atomicAdd(&g_sumsq[t], sq[t]);
    }
}

// ---------------- weight diffs ----------------
__global__ void wdiff1_k(const float* __restrict__ w) {
    int i = blockIdx.x * 256 + threadIdx.x;
    int o = i >> 6, d = i & 63;
    g_wdiff1[i] = w[o * 128 + 64 + d] - w[o * 128 + d];
}
__global__ void wdiff2_k(const float* __restrict__ w) {
    int i = blockIdx.x * 256 + threadIdx.x;
    int o = i >> 7, d = i & 127;
    g_wdiff2[i] = w[o * 256 + 128 + d] - w[o * 256 + d];
}

// ---------------- center feature gathers ----------------
__global__ void gather_cfeat1() {
    int i = blockIdx.x * 256 + threadIdx.x;
    int r = i >> 6, c = i & 63;
    int b = r >> 9;
    int fid = g_fidx1[r];
    float v = g_f[((size_t)(b * NN + fid)) * 64 + c];
    g_cfeat1[i] = fmaxf(v * g_scale[c] + g_shift[c], 0.f);
}
__global__ void gather_cfeat2() {
    int i = blockIdx.x * 256 + threadIdx.x;
    int r = i >> 7, c = i & 127;
    int b = r >> 8;
    int fid = g_fidx2[r];
    g_cfeat2[i] = g_f1[((size_t)(b * S1V + fid)) * 128 + c];
}

// ---------------- pool finish: apply BN+ReLU to raw max/min ----------------
__global__ void pool_finish1() {
    int i = blockIdx.x * 256 + threadIdx.x;   // 8192*128
    int c = i & 127;
    float sc = g_scale[c];
    float v = (sc >= 0.f) ? g_pmax[i] : g_pmin[i];
    g_f1[i] = fmaxf(sc * v + g_shift[c], 0.f);
}
__global__ void pool_finish2(float* __restrict__ out) {
    int i = blockIdx.x * 256 + threadIdx.x;   // 4096*256
    int bs = i >> 8, o = i & 255;
    int b = bs >> 8, s = bs & 255;
    float sc = g_scale[o];
    float v = (sc >= 0.f) ? g_pmax[i] : g_pmin[i];
    out[((size_t)(b * 256 + o)) * 256 + s] = fmaxf(sc * v + g_shift[o], 0.f);
}

// ---------------- launch sequence ----------------
extern "C" void kernel_launch(void* const* d_in, const int* in_sizes, int n_in,
                              void* d_out, int out_size) {
    const float* x     = (const float*)d_in[0];
    const float* w1    = (const float*)d_in[1];
    const float* w2    = (const float*)d_in[2];
    const float* g1    = (const float*)d_in[3];
    const float* b1    = (const float*)d_in[4];
    const float* g2    = (const float*)d_in[5];
    const float* b2    = (const float*)d_in[6];
    const float* s1w1  = (const float*)d_in[7];
    const float* s1w2  = (const float*)d_in[8];
    const float* s1g1  = (const float*)d_in[9];
    const float* s1b1  = (const float*)d_in[10];
    const float* s1g2  = (const float*)d_in[11];
    const float* s1b2  = (const float*)d_in[12];
    const float* s2w1  = (const float*)d_in[13];
    const float* s2w2  = (const float*)d_in[14];
    const float* s2g1  = (const float*)d_in[15];
    const float* s2b1  = (const float*)d_in[16];
    const float* s2g2  = (const float*)d_in[17];
    const float* s2b2  = (const float*)d_in[18];
    float* out = (float*)d_out;

    const int RP = BB * NN;        // 65536
    const int R1 = BB * S1V * KV;  // 262144
    const int R2 = BB * S2V * KV;  // 131072

    prep_coords<<<RP / 256, 256>>>(x);

    // point_cbr 1
    cbr1_kernel<<<RP * 64 / 256, 256>>>(x, w1);
    zero_stats<<<1, 256>>>();
    stats_kernel<<<512, 256>>>(0, RP * 64, 64);
    finalize_stats<<<1, 64>>>(g1, b1, 1.0f / RP);

    // point_cbr 2 (bn-relu fused on load)
    cbr2_kernel<<<RP / 4, 256>>>(w2);
    zero_stats<<<1, 256>>>();
    stats_kernel<<<512, 256>>>(2, RP * 64, 64);
    finalize_stats<<<1, 64>>>(g2, b2, 1.0f / RP);

    // sg1 sampling / knn
    fps_kernel<NN, S1V, 1024, 0><<<BB, 1024>>>();
    gather_c2<<<BB * S1V / 256, 256>>>();
    knn_kernel<NN, S1V, 0><<<BB * S1V / 4, 128>>>();

    // factored sg1 layer 1: G1 = bnrelu(f) @ w1a^T -> zbuf [65536 x 128]
    gemm_k<64, 128, true><<<dim3(512, 1), 256>>>(2, s1w1, -1, 0, 128);
    gather_cfeat1<<<BB * S1V * 64 / 256, 256>>>();
    wdiff1_k<<<128 * 64 / 256, 256>>>(s1w1);
    gemm_k<64, 64, false><<<dim3(64, 1), 256>>>(3, nullptr, 7, 5, 128);

    // y1 stats straight from the gather (no y1 tensor)
    zero_stats<<<1, 256>>>();
    stats_gather_k<128, 0><<<512, 256>>>(R1);
    finalize_stats<<<1, 128>>>(s1g1, s1b1, 1.0f / R1);

    // sg1 layer 2 fused: gather+BN A-load, epilogue max/min + output stats
    zero_stats<<<1, 256>>>();
    gemm2_fused<128, 0><<<dim3(2048, 1), 256>>>(s1w2);
    finalize_stats<<<1, 128>>>(s1g2, s1b2, 1.0f / R1);
    pool_finish1<<<BB * S1V * 128 / 256, 256>>>();

    // sg2 sampling / knn
    fps_kernel<S1V, S2V, 512, 1><<<BB, 512>>>();
    knn_kernel<S1V, S2V, 1><<<BB * S2V / 4, 128>>>();

    // factored sg2 layer 1: G2 = f1 @ w2a^T -> zbuf [8192 x 256]
    gemm_k<128, 256, false><<<dim3(64, 2), 256>>>(9, s2w1, -1, 0, 256);
    gather_cfeat2<<<BB * S2V * 128 / 256, 256>>>();
    wdiff2_k<<<256 * 128 / 256, 256>>>(s2w1);
    gemm_k<128, 128, false><<<dim3(32, 2), 256>>>(4, nullptr, 8, 6, 256);

    // y2 stats from gather
    zero_stats<<<1, 256>>>();
    stats_gather_k<256, 1><<<512, 256>>>(R2);
    finalize_stats<<<1, 256>>>(s2g1, s2b1, 1.0f / R2);

    // sg2 layer 2 fused
    zero_stats<<<1, 256>>>();
    gemm2_fused<256, 1><<<dim3(1024, 2), 256>>>(s2w2);
    finalize_stats<<<1, 256>>>(s2g2, s2b2, 1.0f / R2);
    pool_finish2<<<BB * S2V * 256 / 256, 256>>>(out);
}

// round 13
// speedup vs baseline: 1.6822x; 1.0100x over previous
#include <cuda_runtime.h>

#define BB 16
#define NN 4096
#define S1V 512
#define S2V 256
#define KV 32
#define EPSF 1e-5f

typedef unsigned long long ull;

// ---------------- f32x2 packed-FMA helpers (Blackwell FFMA2) ----------------
__device__ __forceinline__ void ffma2(ull& acc, ull a, ull b) {
    asm volatile("fma.rn.f32x2 %0, %1, %2, %0;" : "+l"(acc) : "l"(a), "l"(b));
}
__device__ __forceinline__ ull splat2(float x) {
    ull r;
    asm("mov.b64 %0, {%1, %1};" : "=l"(r) : "f"(x));
    return r;
}
__device__ __forceinline__ float2 unpk(ull v) {
    float lo, hi;
    asm("mov.b64 {%0, %1}, %2;" : "=f"(lo), "=f"(hi) : "l"(v));
    return make_float2(lo, hi);
}

// ---------------- scratch (static device globals; no allocation) ----------------
__device__ __align__(16) float g_zbuf[33554432];            // ping (G1 / G2 live here)
__device__ __align__(16) float g_f[BB * NN * 64];           // raw cbr2 output (B,N,64)
__device__ __align__(16) float g_f1[BB * S1V * 128];        // sg1 final features (B,S1,128)
__device__ __align__(16) float g_cfeat1[BB * S1V * 64];     // bn-relu'd center feats sg1
__device__ __align__(16) float g_cfeat2[BB * S2V * 128];    // center feats sg2
__device__ __align__(16) float g_c1out[BB * S1V * 128];     // center @ wdiff1^T
__device__ __align__(16) float g_c2out[BB * S2V * 256];     // center @ wdiff2^T
__device__ __align__(16) float g_wdiff1[128 * 64];
__device__ __align__(16) float g_wdiff2[256 * 128];
__device__ __align__(16) float g_pmax[1048576];             // per-center raw max
__device__ __align__(16) float g_pmin[1048576];             // per-center raw min
__device__ float g_cx[BB * NN], g_cy[BB * NN], g_cz[BB * NN];
__device__ float g_c2x[BB * S1V], g_c2y[BB * S1V], g_c2z[BB * S1V];
__device__ int   g_fidx1[BB * S1V], g_fidx2[BB * S2V];
__device__ int   g_knn1[BB * S1V * KV], g_knn2[BB * S2V * KV];
__device__ __align__(16) float g_sum[256], g_sumsq[256];
__device__ __align__(16) float g_scale[256], g_shift[256];

__device__ __forceinline__ float* buf_sel(int w) {
    switch (w) {
        case 0: return g_zbuf;
        case 2: return g_f;
        case 3: return g_cfeat1;
        case 4: return g_cfeat2;
        case 5: return g_c1out;
        case 6: return g_c2out;
        case 7: return g_wdiff1;
        case 8: return g_wdiff2;
        case 9: return g_f1;
    }
    return g_zbuf;
}

// ---------------- coords prep ----------------
__global__ void prep_coords(const float* __restrict__ x) {
    int i = blockIdx.x * 256 + threadIdx.x;
    int b = i >> 12, n = i & 4095;
    const float* xb = x + (size_t)b * 3 * NN;
    g_cx[i] = xb[n];
    g_cy[i] = xb[NN + n];
    g_cz[i] = xb[2 * NN + n];
}

// ---------------- point_cbr stage 1 (raw) ----------------
__global__ void cbr1_kernel(const float* __restrict__ x, const float* __restrict__ w1) {
    int idx = blockIdx.x * 256 + threadIdx.x;
    int r = idx >> 6, o = idx & 63;
    int b = r >> 12, n = r & 4095;
    const float* xb = x + (size_t)b * 3 * NN;
    float v = w1[o * 3 + 0] * xb[n] + w1[o * 3 + 1] * xb[NN + n] + w1[o * 3 + 2] * xb[2 * NN + n];
    g_zbuf[idx] = v;
}

// ---------------- point_cbr stage 2: bnrelu(zbuf) @ w2^T -> g_f (raw) ----------------
__global__ void cbr2_kernel(const float* __restrict__ w2) {
    __shared__ float ys[4][64];
    __shared__ float wst[64 * 64];
    int tid = threadIdx.x;
    int r0 = blockIdx.x * 4;
    for (int j = tid; j < 4096; j += 256) {
        int o = j >> 6, c = j & 63;
        wst[c * 64 + o] = w2[j];
    }
    {
        int c = tid & 63;
        float v = g_zbuf[r0 * 64 + tid];
        v = fmaxf(v * g_scale[c] + g_shift[c], 0.f);
        ((float*)ys)[tid] = v;
    }
    __syncthreads();
    int rl = tid >> 6, o = tid & 63;
    float acc = 0.f;
#pragma unroll 16
    for (int c = 0; c < 64; c++) acc += ys[rl][c] * wst[c * 64 + o];
    g_f[(r0 + rl) * 64 + o] = acc;
}

// ---------------- BN stats / finalize ----------------
__global__ void zero_stats() { g_sum[threadIdx.x] = 0.f; g_sumsq[threadIdx.x] = 0.f; }

__global__ void stats_kernel(int which, int total, int O) {
    const float* z = buf_sel(which);
    int gt = blockIdx.x * 256 + threadIdx.x;
    int stride = gridDim.x * 256;
    float s = 0.f, q = 0.f;
    for (int i = gt; i < total; i += stride) { float v = z[i]; s += v; q += v * v; }
    __shared__ float bs[256], bq[256];
    bs[threadIdx.x] = s; bq[threadIdx.x] = q;
    __syncthreads();
    if (threadIdx.x < O) {
        for (int j = threadIdx.x + O; j < 256; j += O) { s += bs[j]; q += bq[j]; }
        atomicAdd(&g_sum[threadIdx.x], s);
        atomicAdd(&g_sumsq[threadIdx.x], q);
    }
}

__global__ void finalize_stats(const float* __restrict__ g, const float* __restrict__ bias, float invR) {
    int o = threadIdx.x;
    float m = g_sum[o] * invR;
    float v = g_sumsq[o] * invR - m * m;
    float rstd = rsqrtf(v + EPSF);
    float sc = g[o] * rstd;
    g_scale[o] = sc;
    g_shift[o] = bias[o] - m * sc;
}

// ---------------- FPS (bit-exact vs jax scan) ----------------
template <int NPTS, int NSAMP, int TPB, int STAGE>
__global__ void fps_kernel() {
    constexpr int PPT = NPTS / TPB;
    const float* cx = (STAGE == 0) ? g_cx : g_c2x;
    const float* cy = (STAGE == 0) ? g_cy : g_c2y;
    const float* cz = (STAGE == 0) ? g_cz : g_c2z;
    int* fidx = (STAGE == 0) ? g_fidx1 : g_fidx2;
    int b = blockIdx.x, tid = threadIdx.x;
    const float* bx = cx + b * NPTS;
    const float* by = cy + b * NPTS;
    const float* bz = cz + b * NPTS;
    float px[PPT], py[PPT], pz[PPT], dist[PPT];
#pragma unroll
    for (int t = 0; t < PPT; t++) {
        int n = tid + t * TPB;
        px[t] = bx[n]; py[t] = by[n]; pz[t] = bz[n];
        dist[t] = 1e10f;
    }
    __shared__ float wv[TPB / 32];
    __shared__ int wi[TPB / 32];
    __shared__ int s_far;
    int far = 0;
    for (int s = 0; s < NSAMP; s++) {
        if (tid == 0) fidx[b * NSAMP + s] = far;
        float fx = bx[far], fy = by[far], fz = bz[far];
        float bv = -1.0f; int bi = 0x7fffffff;
#pragma unroll
        for (int t = 0; t < PPT; t++) {
            float dx = __fsub_rn(px[t], fx);
            float dy = __fsub_rn(py[t], fy);
            float dz = __fsub_rn(pz[t], fz);
            float d = __fadd_rn(__fadd_rn(__fmul_rn(dx, dx), __fmul_rn(dy, dy)), __fmul_rn(dz, dz));
            float nd = fminf(dist[t], d);
            dist[t] = nd;
            int n = tid + t * TPB;
            if (nd > bv) { bv = nd; bi = n; }
        }
#pragma unroll
        for (int off = 16; off > 0; off >>= 1) {
            float ov = __shfl_down_sync(0xffffffffu, bv, off);
            int oi = __shfl_down_sync(0xffffffffu, bi, off);
            if (ov > bv || (ov == bv && oi < bi)) { bv = ov; bi = oi; }
        }
        if ((tid & 31) == 0) { wv[tid >> 5] = bv; wi[tid >> 5] = bi; }
        __syncthreads();
        if (tid < 32) {
            constexpr int NW = TPB / 32;
            float v2 = (tid < NW) ? wv[tid] : -2.0f;
            int i2 = (tid < NW) ? wi[tid] : 0x7fffffff;
#pragma unroll
            for (int off = 16; off > 0; off >>= 1) {
                float ov = __shfl_down_sync(0xffffffffu, v2, off);
                int oi = __shfl_down_sync(0xffffffffu, i2, off);
                if (ov > v2 || (ov == v2 && oi < i2)) { v2 = ov; i2 = oi; }
            }
            if (tid == 0) s_far = i2;
        }
        __syncthreads();
        far = s_far;
    }
}

// ---------------- gather coords of sg1 sampled points ----------------
__global__ void gather_c2() {
    int i = blockIdx.x * 256 + threadIdx.x;
    int b = i >> 9;
    int id = g_fidx1[i];
    g_c2x[i] = g_cx[b * NN + id];
    g_c2y[i] = g_cy[b * NN + id];
    g_c2z[i] = g_cz[b * NN + id];
}

// ---------------- KNN: warp-resident top-32 ----------------
template <int NPTS, int S, int STAGE>
__global__ void knn_kernel() {
    const float* cx = (STAGE == 0) ? g_cx : g_c2x;
    const float* cy = (STAGE == 0) ? g_cy : g_c2y;
    const float* cz = (STAGE == 0) ? g_cz : g_c2z;
    const int* fidx = (STAGE == 0) ? g_fidx1 : g_fidx2;
    int* knn = (STAGE == 0) ? g_knn1 : g_knn2;

    int gw = (blockIdx.x * blockDim.x + threadIdx.x) >> 5;
    int lane = threadIdx.x & 31;
    int b = gw / S;
    const float* bx = cx + b * NPTS;
    const float* by = cy + b * NPTS;
    const float* bz = cz + b * NPTS;
    int ci = fidx[gw];
    float fx = bx[ci], fy = by[ci], fz = bz[ci];
    float fn = (fx * fx + fy * fy) + fz * fz;

    auto distf = [&](int n) {
        float xx = bx[n], yy = by[n], zz = bz[n];
        float nb = (xx * xx + yy * yy) + zz * zz;
        return fn + nb - 2.0f * (fx * xx + fy * yy + fz * zz);
    };

    float bd = distf(lane);
    int bidx = lane;

    float kv; int kl;
    {
        kv = bd; kl = lane;
#pragma unroll
        for (int off = 16; off > 0; off >>= 1) {
            float ov = __shfl_xor_sync(0xffffffffu, kv, off);
            int ol = __shfl_xor_sync(0xffffffffu, kl, off);
            if (ov > kv || (ov == kv && ol < kl)) { kv = ov; kl = ol; }
        }
    }
    for (int base = 32; base < NPTS; base += 32) {
        int n = base + lane;
        float d = distf(n);
        unsigned m = __ballot_sync(0xffffffffu, d < kv);
        while (m) {
            int src = __ffs(m) - 1;
            m &= m - 1;
            float dc = __shfl_sync(0xffffffffu, d, src);
            int nc = __shfl_sync(0xffffffffu, n, src);
            if (dc < kv) {
                if (lane == kl) { bd = dc; bidx = nc; }
                kv = bd; kl = lane;
#pragma unroll
                for (int off = 16; off > 0; off >>= 1) {
                    float ov = __shfl_xor_sync(0xffffffffu, kv, off);
                    int ol = __shfl_xor_sync(0xffffffffu, kl, off);
                    if (ov > kv || (ov == kv && ol < kl)) { kv = ov; kl = ol; }
                }
            }
        }
    }
    knn[gw * KV + lane] = bidx;
}

// ---------------- smem swizzle ----------------
__device__ __forceinline__ int swz(int col) {
    int blk = col >> 5;
    return (blk << 5) + (((col & 31) + (blk << 2)) & 31);
}

// ---------------- plain swizzled double-buffered SGEMM (FFMA2 core) ----------------
template <int CIN, int WS, bool BNA>
__global__ __launch_bounds__(256) void gemm_k(int asel, const float* __restrict__ Wp_in,
                                              int wsel, int csel, int O) {
    const float* A = buf_sel(asel);
    const float* W = Wp_in ? Wp_in : buf_sel(wsel);
    float* C = buf_sel(csel);
    __shared__ float As[2][8 * 132];
    __shared__ float Bs[2][8 * 132];
    int tid = threadIdx.x;
    int brow = blockIdx.x * 128, bcol = blockIdx.y * 128;
    int tx = tid & 15, ty = tid >> 4;
    int lr = tid >> 1, lc = (tid & 1) * 4;
    const float* Ap = A + (size_t)(brow + lr) * CIN + lc;
    const float* Wp = W + (size_t)(bcol + lr) * WS + lc;
    int wp = swz(lr);
    int sa0 = swz(ty * 8), sa1 = swz(ty * 8 + 4);
    int sb0 = swz(tx * 8), sb1 = swz(tx * 8 + 4);

    float4 av = *(const float4*)Ap;
    float4 wv = *(const float4*)Wp;
    if (BNA) {
        float4 sc = *(const float4*)&g_scale[lc];
        float4 sh = *(const float4*)&g_shift[lc];
        av.x = fmaxf(av.x * sc.x + sh.x, 0.f);
        av.y = fmaxf(av.y * sc.y + sh.y, 0.f);
        av.z = fmaxf(av.z * sc.z + sh.z, 0.f);
        av.w = fmaxf(av.w * sc.w + sh.w, 0.f);
    }
    As[0][(lc + 0) * 132 + wp] = av.x; As[0][(lc + 1) * 132 + wp] = av.y;
    As[0][(lc + 2) * 132 + wp] = av.z; As[0][(lc + 3) * 132 + wp] = av.w;
    Bs[0][(lc + 0) * 132 + wp] = wv.x; Bs[0][(lc + 1) * 132 + wp] = wv.y;
    Bs[0][(lc + 2) * 132 + wp] = wv.z; Bs[0][(lc + 3) * 132 + wp] = wv.w;
    __syncthreads();

    ull acc2[8][4];
#pragma unroll
    for (int i = 0; i < 8; i++)
#pragma unroll
        for (int j = 0; j < 4; j++) acc2[i][j] = 0ull;

    constexpr int NIT = CIN / 8;
#pragma unroll 2
    for (int it = 0; it < NIT; it++) {
        int cur = it & 1;
        float4 av2, wv2;
        if (it + 1 < NIT) {
            av2 = *(const float4*)(Ap + (it + 1) * 8);
            wv2 = *(const float4*)(Wp + (it + 1) * 8);
            if (BNA) {
                float4 sc = *(const float4*)&g_scale[(it + 1) * 8 + lc];
                float4 sh = *(const float4*)&g_shift[(it + 1) * 8 + lc];
                av2.x = fmaxf(av2.x * sc.x + sh.x, 0.f);
                av2.y = fmaxf(av2.y * sc.y + sh.y, 0.f);
                av2.z = fmaxf(av2.z * sc.z + sh.z, 0.f);
                av2.w = fmaxf(av2.w * sc.w + sh.w, 0.f);
            }
        }
#pragma unroll
        for (int k = 0; k < 8; k++) {
            float4 a0 = *(const float4*)&As[cur][k * 132 + sa0];
            float4 a1 = *(const float4*)&As[cur][k * 132 + sa1];
            ulonglong2 bp0 = *(const ulonglong2*)&Bs[cur][k * 132 + sb0];
            ulonglong2 bp1 = *(const ulonglong2*)&Bs[cur][k * 132 + sb1];
            float a[8] = {a0.x, a0.y, a0.z, a0.w, a1.x, a1.y, a1.z, a1.w};
            ull bp[4] = {bp0.x, bp0.y, bp1.x, bp1.y};
#pragma unroll
            for (int i = 0; i < 8; i++) {
                ull as = splat2(a[i]);
#pragma unroll
                for (int j = 0; j < 4; j++) ffma2(acc2[i][j], as, bp[j]);
            }
        }
        if (it + 1 < NIT) {
            int nxt = 1 - cur;
            As[nxt][(lc + 0) * 132 + wp] = av2.x; As[nxt][(lc + 1) * 132 + wp] = av2.y;
            As[nxt][(lc + 2) * 132 + wp] = av2.z; As[nxt][(lc + 3) * 132 + wp] = av2.w;
            Bs[nxt][(lc + 0) * 132 + wp] = wv2.x; Bs[nxt][(lc + 1) * 132 + wp] = wv2.y;
            Bs[nxt][(lc + 2) * 132 + wp] = wv2.z; Bs[nxt][(lc + 3) * 132 + wp] = wv2.w;
            __syncthreads();
        }
    }
#pragma unroll
    for (int i = 0; i < 8; i++) {
        int r = brow + ty * 8 + i;
        float4* cp = (float4*)(C + (size_t)r * O + bcol + tx * 8);
        float2 p0 = unpk(acc2[i][0]), p1 = unpk(acc2[i][1]);
        float2 p2 = unpk(acc2[i][2]), p3 = unpk(acc2[i][3]);
        cp[0] = make_float4(p0.x, p0.y, p1.x, p1.y);
        cp[1] = make_float4(p2.x, p2.y, p3.x, p3.y);
    }
}

// ---------------- FUSED layer-2 GEMM: gather+add+BN-ReLU on A-load,
//                  epilogue = per-center max/min + per-col sum/sumsq (FFMA2 core) ----
template <int CIN, int STAGE>
__global__ __launch_bounds__(256) void gemm2_fused(const float* __restrict__ W) {
    const float* G = g_zbuf;
    const float* C = (STAGE == 0) ? g_c1out : g_c2out;
    const int* knn = (STAGE == 0) ? g_knn1 : g_knn2;
    constexpr int NPTS = (STAGE == 0) ? NN : S1V;
    constexpr int BSH = (STAGE == 0) ? 9 : 8;

    __shared__ float As[2][8 * 132];
    __shared__ float Bs[2][8 * 132];
    int tid = threadIdx.x;
    int brow = blockIdx.x * 128, bcol = blockIdx.y * 128;
    int tx = tid & 15, ty = tid >> 4;
    int lr = tid >> 1, lc = (tid & 1) * 4;

    int grow = brow + lr;
    int nb = knn[grow];
    int bs = grow >> 5;
    int b = bs >> BSH;
    const float* Gp = G + ((size_t)(b * NPTS + nb)) * CIN + lc;
    const float* Cp = C + (size_t)bs * CIN + lc;
    const float* Wp = W + (size_t)(bcol + lr) * CIN + lc;
    int wp = swz(lr);
    int sa0 = swz(ty * 8), sa1 = swz(ty * 8 + 4);
    int sb0 = swz(tx * 8), sb1 = swz(tx * 8 + 4);

    // panel 0
    {
        float4 gv = *(const float4*)Gp;
        float4 cv = *(const float4*)Cp;
        float4 wv = *(const float4*)Wp;
        float4 sc = *(const float4*)&g_scale[lc];
        float4 sh = *(const float4*)&g_shift[lc];
        float ax = fmaxf((gv.x + cv.x) * sc.x + sh.x, 0.f);
        float ay = fmaxf((gv.y + cv.y) * sc.y + sh.y, 0.f);
        float az = fmaxf((gv.z + cv.z) * sc.z + sh.z, 0.f);
        float aw = fmaxf((gv.w + cv.w) * sc.w + sh.w, 0.f);
        As[0][(lc + 0) * 132 + wp] = ax; As[0][(lc + 1) * 132 + wp] = ay;
        As[0][(lc + 2) * 132 + wp] = az; As[0][(lc + 3) * 132 + wp] = aw;
        Bs[0][(lc + 0) * 132 + wp] = wv.x; Bs[0][(lc + 1) * 132 + wp] = wv.y;
        Bs[0][(lc + 2) * 132 + wp] = wv.z; Bs[0][(lc + 3) * 132 + wp] = wv.w;
    }
    __syncthreads();

    ull acc2[8][4];
#pragma unroll
    for (int i = 0; i < 8; i++)
#pragma unroll
        for (int j = 0; j < 4; j++) acc2[i][j] = 0ull;

    constexpr int NIT = CIN / 8;
#pragma unroll 2
    for (int it = 0; it < NIT; it++) {
        int cur = it & 1;
        float axp, ayp, azp, awp;
        float4 wv2;
        if (it + 1 < NIT) {
            float4 gv = *(const float4*)(Gp + (it + 1) * 8);
            float4 cv = *(const float4*)(Cp + (it + 1) * 8);
            wv2 = *(const float4*)(Wp + (it + 1) * 8);
            float4 sc = *(const float4*)&g_scale[(it + 1) * 8 + lc];
            float4 sh = *(const float4*)&g_shift[(it + 1) * 8 + lc];
            axp = fmaxf((gv.x + cv.x) * sc.x + sh.x, 0.f);
            ayp = fmaxf((gv.y + cv.y) * sc.y + sh.y, 0.f);
            azp = fmaxf((gv.z + cv.z) * sc.z + sh.z, 0.f);
            awp = fmaxf((gv.w + cv.w) * sc.w + sh.w, 0.f);
        }
#pragma unroll
        for (int k = 0; k < 8; k++) {
            float4 a0 = *(const float4*)&As[cur][k * 132 + sa0];
            float4 a1 = *(const float4*)&As[cur][k * 132 + sa1];
            ulonglong2 bp0 = *(const ulonglong2*)&Bs[cur][k * 132 + sb0];
            ulonglong2 bp1 = *(const ulonglong2*)&Bs[cur][k * 132 + sb1];
            float a[8] = {a0.x, a0.y, a0.z, a0.w, a1.x, a1.y, a1.z, a1.w};
            ull bp[4] = {bp0.x, bp0.y, bp1.x, bp1.y};
#pragma unroll
            for (int i = 0; i < 8; i++) {
                ull as = splat2(a[i]);
#pragma unroll
                for (int j = 0; j < 4; j++) ffma2(acc2[i][j], as, bp[j]);
            }
        }
        if (it + 1 < NIT) {
            int nxt = 1 - cur;
            As[nxt][(lc + 0) * 132 + wp] = axp; As[nxt][(lc + 1) * 132 + wp] = ayp;
            As[nxt][(lc + 2) * 132 + wp] = azp; As[nxt][(lc + 3) * 132 + wp] = awp;
            Bs[nxt][(lc + 0) * 132 + wp] = wv2.x; Bs[nxt][(lc + 1) * 132 + wp] = wv2.y;
            Bs[nxt][(lc + 2) * 132 + wp] = wv2.z; Bs[nxt][(lc + 3) * 132 + wp] = wv2.w;
            __syncthreads();
        }
    }

    // ---- epilogue: per-thread partials over its 8 rows ----
    float tmax[8], tmin[8], tsum[8], tsq[8];
#pragma unroll
    for (int j = 0; j < 8; j++) { tmax[j] = -1e30f; tmin[j] = 1e30f; tsum[j] = 0.f; tsq[j] = 0.f; }
#pragma unroll
    for (int i = 0; i < 8; i++)
#pragma unroll
        for (int jp = 0; jp < 4; jp++) {
            float2 p = unpk(acc2[i][jp]);
            int j0 = jp * 2;
            tmax[j0] = fmaxf(tmax[j0], p.x);
            tmin[j0] = fminf(tmin[j0], p.x);
            tsum[j0] += p.x;
            tsq[j0] += p.x * p.x;
            tmax[j0 + 1] = fmaxf(tmax[j0 + 1], p.y);
            tmin[j0 + 1] = fminf(tmin[j0 + 1], p.y);
            tsum[j0 + 1] += p.y;
            tsq[j0 + 1] += p.y * p.y;
        }

    float* redA = &As[0][0];   // 2112 floats, used as [16][132]
    float* redB = &Bs[0][0];
    __syncthreads();
#pragma unroll
    for (int j = 0; j < 8; j++) {
        redA[ty * 132 + tx * 8 + j] = tmax[j];
        redB[ty * 132 + tx * 8 + j] = tmin[j];
    }
    __syncthreads();
    {
        int ct = tid >> 6;                  // center within block (0..3)
        int base = (tid & 63) * 2;
        int bs0 = brow >> 5;
#pragma unroll
        for (int u = 0; u < 2; u++) {
            int col = base + u;
            float m = -1e30f, mn = 1e30f;
#pragma unroll
            for (int v = 0; v < 4; v++) {
                m = fmaxf(m, redA[(ct * 4 + v) * 132 + col]);
                mn = fminf(mn, redB[(ct * 4 + v) * 132 + col]);
            }
            size_t o = (size_t)(bs0 + ct) * CIN + bcol + col;
            g_pmax[o] = m;
            g_pmin[o] = mn;
        }
    }
    __syncthreads();
#pragma unroll
    for (int j = 0; j < 8; j++) {
        redA[ty * 132 + tx * 8 + j] = tsum[j];
        redB[ty * 132 + tx * 8 + j] = tsq[j];
    }
    __syncthreads();
    if (tid < 128) {
        float s = 0.f;
#pragma unroll
        for (int v = 0; v < 16; v++) s += redA[v * 132 + tid];
        atomicAdd(&g_sum[bcol + tid], s);
    } else {
        int col = tid - 128;
        float s = 0.f;
#pragma unroll
        for (int v = 0; v < 16; v++) s += redB[v * 132 + col];
        atomicAdd(&g_sumsq[bcol + col], s);
    }
}

// ---------------- gather-stats for y = G[nb] + C[center] ----------------
template <int CIN, int STAGE>
__global__ void stats_gather_k(int R) {
    const float* G = g_zbuf;
    const float* C = (STAGE == 0) ? g_c1out : g_c2out;
    const int* knn = (STAGE == 0) ? g_knn1 : g_knn2;
    constexpr int NPTS = (STAGE == 0) ? NN : S1V;
    constexpr int BSH = (STAGE == 0) ? 9 : 8;
    constexpr int NSEG = CIN / 128;

    int wid = (blockIdx.x * blockDim.x + threadIdx.x) >> 5;
    int lane = threadIdx.x & 31;
    int nw = (gridDim.x * blockDim.x) >> 5;
    float s[NSEG][4], q[NSEG][4];
#pragma unroll
    for (int sg = 0; sg < NSEG; sg++)
#pragma unroll
        for (int j = 0; j < 4; j++) { s[sg][j] = 0.f; q[sg][j] = 0.f; }

    for (int row = wid; row < R; row += nw) {
        int nb = knn[row];
        int bs = row >> 5;
        int b = bs >> BSH;
        size_t gb = ((size_t)(b * NPTS + nb)) * CIN;
        size_t cb = (size_t)bs * CIN;
#pragma unroll
        for (int sg = 0; sg < NSEG; sg++) {
            int col = sg * 128 + lane * 4;
            float4 g = *(const float4*)(G + gb + col);
            float4 c = *(const float4*)(C + cb + col);
            float y0 = g.x + c.x, y1 = g.y + c.y, y2 = g.z + c.z, y3 = g.w + c.w;
            s[sg][0] += y0; s[sg][1] += y1; s[sg][2] += y2; s[sg][3] += y3;
            q[sg][0] += y0 * y0; q[sg][1] += y1 * y1; q[sg][2] += y2 * y2; q[sg][3] += y3 * y3;
        }
    }
    __shared__ float ss[CIN], sq[CIN];
    for (int t = threadIdx.x; t < CIN; t += 256) { ss[t] = 0.f; sq[t] = 0.f; }
    __syncthreads();
#pragma unroll
    for (int sg = 0; sg < NSEG; sg++)
#pragma unroll
        for (int j = 0; j < 4; j++) {
            atomicAdd(&ss[sg * 128 + lane * 4 + j], s[sg][j]);
            atomicAdd(&sq[sg * 128 + lane * 4 + j], q[sg][j]);
        }
    __syncthreads();
    for (int t = threadIdx.x; t < CIN; t += 256) {
        atomicAdd(&g_sum[t], ss[t]);
        atomicAdd(&g_sumsq[t], sq[t]);
    }
}

// ---------------- weight diffs ----------------
__global__ void wdiff1_k(const float* __restrict__ w) {
    int i = blockIdx.x * 256 + threadIdx.x;
    int o = i >> 6, d = i & 63;
    g_wdiff1[i] = w[o * 128 + 64 + d] - w[o * 128 + d];
}
__global__ void wdiff2_k(const float* __restrict__ w) {
    int i = blockIdx.x * 256 + threadIdx.x;
    int o = i >> 7, d = i & 127;
    g_wdiff2[i] = w[o * 256 + 128 + d] - w[o * 256 + d];
}

// ---------------- center feature gathers ----------------
__global__ void gather_cfeat1() {
    int i = blockIdx.x * 256 + threadIdx.x;
    int r = i >> 6, c = i & 63;
    int b = r >> 9;
    int fid = g_fidx1[r];
    float v = g_f[((size_t)(b * NN + fid)) * 64 + c];
    g_cfeat1[i] = fmaxf(v * g_scale[c] + g_shift[c], 0.f);
}
__global__ void gather_cfeat2() {
    int i = blockIdx.x * 256 + threadIdx.x;
    int r = i >> 7, c = i & 127;
    int b = r >> 8;
    int fid = g_fidx2[r];
    g_cfeat2[i] = g_f1[((size_t)(b * S1V + fid)) * 128 + c];
}

// ---------------- pool finish: apply BN+ReLU to raw max/min ----------------
__global__ void pool_finish1() {
    int i = blockIdx.x * 256 + threadIdx.x;   // 8192*128
    int c = i & 127;
    float sc = g_scale[c];
    float v = (sc >= 0.f) ? g_pmax[i] : g_pmin[i];
    g_f1[i] = fmaxf(sc * v + g_shift[c], 0.f);
}
__global__ void pool_finish2(float* __restrict__ out) {
    int i = blockIdx.x * 256 + threadIdx.x;   // 4096*256
    int bs = i >> 8, o = i & 255;
    int b = bs >> 8, s = bs & 255;
    float sc = g_scale[o];
    float v = (sc >= 0.f) ? g_pmax[i] : g_pmin[i];
    out[((size_t)(b * 256 + o)) * 256 + s] = fmaxf(sc * v + g_shift[o], 0.f);
}

// ---------------- launch sequence ----------------
extern "C" void kernel_launch(void* const* d_in, const int* in_sizes, int n_in,
                              void* d_out, int out_size) {
    const float* x     = (const float*)d_in[0];
    const float* w1    = (const float*)d_in[1];
    const float* w2    = (const float*)d_in[2];
    const float* g1    = (const float*)d_in[3];
    const float* b1    = (const float*)d_in[4];
    const float* g2    = (const float*)d_in[5];
    const float* b2    = (const float*)d_in[6];
    const float* s1w1  = (const float*)d_in[7];
    const float* s1w2  = (const float*)d_in[8];
    const float* s1g1  = (const float*)d_in[9];
    const float* s1b1  = (const float*)d_in[10];
    const float* s1g2  = (const float*)d_in[11];
    const float* s1b2  = (const float*)d_in[12];
    const float* s2w1  = (const float*)d_in[13];
    const float* s2w2  = (const float*)d_in[14];
    const float* s2g1  = (const float*)d_in[15];
    const float* s2b1  = (const float*)d_in[16];
    const float* s2g2  = (const float*)d_in[17];
    const float* s2b2  = (const float*)d_in[18];
    float* out = (float*)d_out;

    const int RP = BB * NN;        // 65536
    const int R1 = BB * S1V * KV;  // 262144
    const int R2 = BB * S2V * KV;  // 131072

    prep_coords<<<RP / 256, 256>>>(x);

    // point_cbr 1
    cbr1_kernel<<<RP * 64 / 256, 256>>>(x, w1);
    zero_stats<<<1, 256>>>();
    stats_kernel<<<512, 256>>>(0, RP * 64, 64);
    finalize_stats<<<1, 64>>>(g1, b1, 1.0f / RP);

    // point_cbr 2 (bn-relu fused on load)
    cbr2_kernel<<<RP / 4, 256>>>(w2);
    zero_stats<<<1, 256>>>();
    stats_kernel<<<512, 256>>>(2, RP * 64, 64);
    finalize_stats<<<1, 64>>>(g2, b2, 1.0f / RP);

    // sg1 sampling / knn
    fps_kernel<NN, S1V, 1024, 0><<<BB, 1024>>>();
    gather_c2<<<BB * S1V / 256, 256>>>();
    knn_kernel<NN, S1V, 0><<<BB * S1V / 4, 128>>>();

    // factored sg1 layer 1: G1 = bnrelu(f) @ w1a^T -> zbuf [65536 x 128]
    gemm_k<64, 128, true><<<dim3(512, 1), 256>>>(2, s1w1, -1, 0, 128);
    gather_cfeat1<<<BB * S1V * 64 / 256, 256>>>();
    wdiff1_k<<<128 * 64 / 256, 256>>>(s1w1);
    gemm_k<64, 64, false><<<dim3(64, 1), 256>>>(3, nullptr, 7, 5, 128);

    // y1 stats straight from the gather (no y1 tensor)
    zero_stats<<<1, 256>>>();
    stats_gather_k<128, 0><<<512, 256>>>(R1);
    finalize_stats<<<1, 128>>>(s1g1, s1b1, 1.0f / R1);

    // sg1 layer 2 fused: gather+BN A-load, epilogue max/min + output stats
    zero_stats<<<1, 256>>>();
    gemm2_fused<128, 0><<<dim3(2048, 1), 256>>>(s1w2);
    finalize_stats<<<1, 128>>>(s1g2, s1b2, 1.0f / R1);
    pool_finish1<<<BB * S1V * 128 / 256, 256>>>();

    // sg2 sampling / knn
    fps_kernel<S1V, S2V, 512, 1><<<BB, 512>>>();
    knn_kernel<S1V, S2V, 1><<<BB * S2V / 4, 128>>>();

    // factored sg2 layer 1: G2 = f1 @ w2a^T -> zbuf [8192 x 256]
    gemm_k<128, 256, false><<<dim3(64, 2), 256>>>(9, s2w1, -1, 0, 256);
    gather_cfeat2<<<BB * S2V * 128 / 256, 256>>>();
    wdiff2_k<<<256 * 128 / 256, 256>>>(s2w1);
    gemm_k<128, 128, false><<<dim3(32, 2), 256>>>(4, nullptr, 8, 6, 256);

    // y2 stats from gather
    zero_stats<<<1, 256>>>();
    stats_gather_k<256, 1><<<512, 256>>>(R2);
    finalize_stats<<<1, 256>>>(s2g1, s2b1, 1.0f / R2);

    // sg2 layer 2 fused
    zero_stats<<<1, 256>>>();
    gemm2_fused<256, 1><<<dim3(1024, 2), 256>>>(s2w2);
    finalize_stats<<<1, 256>>>(s2g2, s2b2, 1.0f / R2);
    pool_finish2<<<BB * S2V * 256 / 256, 256>>>(out);
}

// round 14
// speedup vs baseline: 2.3778x; 1.4135x over previous
#include <cuda_runtime.h>

#define BB 16
#define NN 4096
#define S1V 512
#define S2V 256
#define KV 32
#define EPSF 1e-5f

typedef unsigned long long ull;

// ---------------- f32x2 packed-FMA helpers ----------------
__device__ __forceinline__ void ffma2(ull& acc, ull a, ull b) {
    asm volatile("fma.rn.f32x2 %0, %1, %2, %0;" : "+l"(acc) : "l"(a), "l"(b));
}
__device__ __forceinline__ ull splat2(float x) {
    ull r;
    asm("mov.b64 %0, {%1, %1};" : "=l"(r) : "f"(x));
    return r;
}
__device__ __forceinline__ float2 unpk(ull v) {
    float lo, hi;
    asm("mov.b64 {%0, %1}, %2;" : "=f"(lo), "=f"(hi) : "l"(v));
    return make_float2(lo, hi);
}

// ---------------- scratch ----------------
__device__ __align__(16) float g_zbuf[33554432];
__device__ __align__(16) float g_f[BB * NN * 64];
__device__ __align__(16) float g_f1[BB * S1V * 128];
__device__ __align__(16) float g_cfeat1[BB * S1V * 64];
__device__ __align__(16) float g_cfeat2[BB * S2V * 128];
__device__ __align__(16) float g_c1out[BB * S1V * 128];
__device__ __align__(16) float g_c2out[BB * S2V * 256];
__device__ __align__(16) float g_wdiff1[128 * 64];
__device__ __align__(16) float g_wdiff2[256 * 128];
__device__ __align__(16) float g_pmax[1048576];
__device__ __align__(16) float g_pmin[1048576];
__device__ float g_cx[BB * NN], g_cy[BB * NN], g_cz[BB * NN];
__device__ float g_c2x[BB * S1V], g_c2y[BB * S1V], g_c2z[BB * S1V];
__device__ int   g_fidx1[BB * S1V], g_fidx2[BB * S2V];
__device__ int   g_knn1[BB * S1V * KV], g_knn2[BB * S2V * KV];
__device__ __align__(16) float g_sum[256], g_sumsq[256];
__device__ __align__(16) float g_scale[256], g_shift[256];

__device__ __forceinline__ float* buf_sel(int w) {
    switch (w) {
        case 0: return g_zbuf;
        case 2: return g_f;
        case 3: return g_cfeat1;
        case 4: return g_cfeat2;
        case 5: return g_c1out;
        case 6: return g_c2out;
        case 7: return g_wdiff1;
        case 8: return g_wdiff2;
        case 9: return g_f1;
    }
    return g_zbuf;
}

// ---------------- coords prep ----------------
__global__ void prep_coords(const float* __restrict__ x) {
    int i = blockIdx.x * 256 + threadIdx.x;
    int b = i >> 12, n = i & 4095;
    const float* xb = x + (size_t)b * 3 * NN;
    g_cx[i] = xb[n];
    g_cy[i] = xb[NN + n];
    g_cz[i] = xb[2 * NN + n];
}

// ---------------- point_cbr stage 1 (fused stats) ----------------
__global__ void cbr1_kernel(const float* __restrict__ x, const float* __restrict__ w1) {
    __shared__ float ws[192];
    int tid = threadIdx.x;
    if (tid < 192) ws[tid] = w1[tid];
    __syncthreads();
    int o = tid & 63;
    float wa = ws[o * 3 + 0], wb = ws[o * 3 + 1], wc = ws[o * 3 + 2];
    float s = 0.f, q = 0.f;
    for (int i = blockIdx.x * 256 + tid; i < BB * NN * 64; i += 512 * 256) {
        int r = i >> 6;
        int b = r >> 12, n = r & 4095;
        const float* xb = x + (size_t)b * 3 * NN;
        float v = wa * xb[n] + wb * xb[NN + n] + wc * xb[2 * NN + n];
        g_zbuf[i] = v;
        s += v; q += v * v;
    }
    __shared__ float bs[256], bq[256];
    bs[tid] = s; bq[tid] = q;
    __syncthreads();
    if (tid < 64) {
        for (int j = tid + 64; j < 256; j += 64) { s += bs[j]; q += bq[j]; }
        atomicAdd(&g_sum[tid], s);
        atomicAdd(&g_sumsq[tid], q);
    }
}

// ---------------- point_cbr stage 2 (persistent blocks, fused stats) ----------------
__global__ void cbr2_kernel(const float* __restrict__ w2) {
    __shared__ float ys[4][64];
    __shared__ float wst[64 * 64];
    int tid = threadIdx.x;
    for (int j = tid; j < 4096; j += 256) {
        int o = j >> 6, c = j & 63;
        wst[c * 64 + o] = w2[j];
    }
    int rl = tid >> 6, o = tid & 63;
    float scl = g_scale[o], shf = g_shift[o];
    float s = 0.f, q = 0.f;
    for (int it = 0; it < 32; it++) {
        int r0 = (blockIdx.x * 32 + it) * 4;
        __syncthreads();
        {
            float v = g_zbuf[r0 * 64 + tid];
            v = fmaxf(v * scl + shf, 0.f);
            ((float*)ys)[tid] = v;
        }
        __syncthreads();
        float acc = 0.f;
#pragma unroll 16
        for (int c = 0; c < 64; c++) acc += ys[rl][c] * wst[c * 64 + o];
        g_f[(r0 + rl) * 64 + o] = acc;
        s += acc; q += acc * acc;
    }
    __shared__ float bs[256], bq[256];
    bs[tid] = s; bq[tid] = q;
    __syncthreads();
    if (tid < 64) {
        for (int j = tid + 64; j < 256; j += 64) { s += bs[j]; q += bq[j]; }
        atomicAdd(&g_sum[tid], s);
        atomicAdd(&g_sumsq[tid], q);
    }
}

// ---------------- finalize (zeroes accumulators for next use) ----------------
__global__ void finalize_stats(const float* __restrict__ g, const float* __restrict__ bias,
                               float invR, int O) {
    int o = threadIdx.x;   // 256
    float su = g_sum[o], sq = g_sumsq[o];
    g_sum[o] = 0.f; g_sumsq[o] = 0.f;
    if (o < O) {
        float m = su * invR;
        float v = sq * invR - m * m;
        float rstd = rsqrtf(v + EPSF);
        float sc = g[o] * rstd;
        g_scale[o] = sc;
        g_shift[o] = bias[o] - m * sc;
    }
}

// ---------------- FPS (bit-exact; REDUX argmax) ----------------
template <int NPTS, int NSAMP, int TPB, int STAGE>
__global__ void fps_kernel() {
    constexpr int PPT = NPTS / TPB;
    constexpr int NW = TPB / 32;
    const float* cx = (STAGE == 0) ? g_cx : g_c2x;
    const float* cy = (STAGE == 0) ? g_cy : g_c2y;
    const float* cz = (STAGE == 0) ? g_cz : g_c2z;
    int* fidx = (STAGE == 0) ? g_fidx1 : g_fidx2;
    int b = blockIdx.x, tid = threadIdx.x;
    const float* bx = cx + b * NPTS;
    const float* by = cy + b * NPTS;
    const float* bz = cz + b * NPTS;
    float px[PPT], py[PPT], pz[PPT], dist[PPT];
#pragma unroll
    for (int t = 0; t < PPT; t++) {
        int n = tid + t * TPB;
        px[t] = bx[n]; py[t] = by[n]; pz[t] = bz[n];
        dist[t] = 1e10f;
    }
    __shared__ unsigned wv[NW];
    __shared__ unsigned wi[NW];
    __shared__ int s_far;
    int far = 0;
    for (int s = 0; s < NSAMP; s++) {
        if (tid == 0) fidx[b * NSAMP + s] = far;
        float fx = bx[far], fy = by[far], fz = bz[far];
        float bv = -1.0f; int bi = 0x7fffffff;
#pragma unroll
        for (int t = 0; t < PPT; t++) {
            float dx = __fsub_rn(px[t], fx);
            float dy = __fsub_rn(py[t], fy);
            float dz = __fsub_rn(pz[t], fz);
            float d = __fadd_rn(__fadd_rn(__fmul_rn(dx, dx), __fmul_rn(dy, dy)), __fmul_rn(dz, dz));
            float nd = fminf(dist[t], d);
            dist[t] = nd;
            int n = tid + t * TPB;
            if (nd > bv) { bv = nd; bi = n; }   // lowest n on tie within thread
        }
        // warp argmax via REDUX (dist >= 0 so float bits are uint-monotonic)
        unsigned uv = __float_as_uint(bv);
        unsigned vmax = __reduce_max_sync(0xffffffffu, uv);
        unsigned cand = (uv == vmax) ? (unsigned)bi : 0xffffffffu;
        unsigned imin = __reduce_min_sync(0xffffffffu, cand);
        if ((tid & 31) == 0) { wv[tid >> 5] = vmax; wi[tid >> 5] = imin; }
        __syncthreads();
        if (tid < 32) {
            unsigned uv2 = (tid < NW) ? wv[tid] : 0u;
            unsigned i2 = (tid < NW) ? wi[tid] : 0xffffffffu;
            unsigned vm2 = __reduce_max_sync(0xffffffffu, uv2);
            unsigned c2 = (uv2 == vm2) ? i2 : 0xffffffffu;
            unsigned im2 = __reduce_min_sync(0xffffffffu, c2);
            if (tid == 0) s_far = (int)im2;
        }
        __syncthreads();
        far = s_far;
    }
}

// ---------------- gather coords of sg1 sampled points ----------------
__global__ void gather_c2() {
    int i = blockIdx.x * 256 + threadIdx.x;
    int b = i >> 9;
    int id = g_fidx1[i];
    g_c2x[i] = g_cx[b * NN + id];
    g_c2y[i] = g_cy[b * NN + id];
    g_c2z[i] = g_cz[b * NN + id];
}

// ---------------- KNN: warp-resident top-32 ----------------
template <int NPTS, int S, int STAGE>
__global__ void knn_kernel() {
    const float* cx = (STAGE == 0) ? g_cx : g_c2x;
    const float* cy = (STAGE == 0) ? g_cy : g_c2y;
    const float* cz = (STAGE == 0) ? g_cz : g_c2z;
    const int* fidx = (STAGE == 0) ? g_fidx1 : g_fidx2;
    int* knn = (STAGE == 0) ? g_knn1 : g_knn2;

    int gw = (blockIdx.x * blockDim.x + threadIdx.x) >> 5;
    int lane = threadIdx.x & 31;
    int b = gw / S;
    const float* bx = cx + b * NPTS;
    const float* by = cy + b * NPTS;
    const float* bz = cz + b * NPTS;
    int ci = fidx[gw];
    float fx = bx[ci], fy = by[ci], fz = bz[ci];
    float fn = (fx * fx + fy * fy) + fz * fz;

    auto distf = [&](int n) {
        float xx = bx[n], yy = by[n], zz = bz[n];
        float nb = (xx * xx + yy * yy) + zz * zz;
        return fn + nb - 2.0f * (fx * xx + fy * yy + fz * zz);
    };

    float bd = distf(lane);
    int bidx = lane;

    float kv; int kl;
    {
        kv = bd; kl = lane;
#pragma unroll
        for (int off = 16; off > 0; off >>= 1) {
            float ov = __shfl_xor_sync(0xffffffffu, kv, off);
            int ol = __shfl_xor_sync(0xffffffffu, kl, off);
            if (ov > kv || (ov == kv && ol < kl)) { kv = ov; kl = ol; }
        }
    }
    for (int base = 32; base < NPTS; base += 32) {
        int n = base + lane;
        float d = distf(n);
        unsigned m = __ballot_sync(0xffffffffu, d < kv);
        while (m) {
            int src = __ffs(m) - 1;
            m &= m - 1;
            float dc = __shfl_sync(0xffffffffu, d, src);
            int nc = __shfl_sync(0xffffffffu, n, src);
            if (dc < kv) {
                if (lane == kl) { bd = dc; bidx = nc; }
                kv = bd; kl = lane;
#pragma unroll
                for (int off = 16; off > 0; off >>= 1) {
                    float ov = __shfl_xor_sync(0xffffffffu, kv, off);
                    int ol = __shfl_xor_sync(0xffffffffu, kl, off);
                    if (ov > kv || (ov == kv && ol < kl)) { kv = ov; kl = ol; }
                }
            }
        }
    }
    knn[gw * KV + lane] = bidx;
}

// ---------------- smem swizzle ----------------
__device__ __forceinline__ int swz(int col) {
    int blk = col >> 5;
    return (blk << 5) + (((col & 31) + (blk << 2)) & 31);
}

// ---------------- plain swizzled double-buffered SGEMM (FFMA2 core) ----------------
template <int CIN, int WS, bool BNA>
__global__ __launch_bounds__(256) void gemm_k(int asel, const float* __restrict__ Wp_in,
                                              int wsel, int csel, int O) {
    const float* A = buf_sel(asel);
    const float* W = Wp_in ? Wp_in : buf_sel(wsel);
    float* C = buf_sel(csel);
    __shared__ float As[2][8 * 132];
    __shared__ float Bs[2][8 * 132];
    int tid = threadIdx.x;
    int brow = blockIdx.x * 128, bcol = blockIdx.y * 128;
    int tx = tid & 15, ty = tid >> 4;
    int lr = tid >> 1, lc = (tid & 1) * 4;
    const float* Ap = A + (size_t)(brow + lr) * CIN + lc;
    const float* Wp = W + (size_t)(bcol + lr) * WS + lc;
    int wp = swz(lr);
    int sa0 = swz(ty * 8), sa1 = swz(ty * 8 + 4);
    int sb0 = swz(tx * 8), sb1 = swz(tx * 8 + 4);

    float4 av = *(const float4*)Ap;
    float4 wv = *(const float4*)Wp;
    if (BNA) {
        float4 sc = *(const float4*)&g_scale[lc];
        float4 sh = *(const float4*)&g_shift[lc];
        av.x = fmaxf(av.x * sc.x + sh.x, 0.f);
        av.y = fmaxf(av.y * sc.y + sh.y, 0.f);
        av.z = fmaxf(av.z * sc.z + sh.z, 0.f);
        av.w = fmaxf(av.w * sc.w + sh.w, 0.f);
    }
    As[0][(lc + 0) * 132 + wp] = av.x; As[0][(lc + 1) * 132 + wp] = av.y;
    As[0][(lc + 2) * 132 + wp] = av.z; As[0][(lc + 3) * 132 + wp] = av.w;
    Bs[0][(lc + 0) * 132 + wp] = wv.x; Bs[0][(lc + 1) * 132 + wp] = wv.y;
    Bs[0][(lc + 2) * 132 + wp] = wv.z; Bs[0][(lc + 3) * 132 + wp] = wv.w;
    __syncthreads();

    ull acc2[8][4];
#pragma unroll
    for (int i = 0; i < 8; i++)
#pragma unroll
        for (int j = 0; j < 4; j++) acc2[i][j] = 0ull;

    constexpr int NIT = CIN / 8;
#pragma unroll 2
    for (int it = 0; it < NIT; it++) {
        int cur = it & 1;
        float4 av2, wv2;
        if (it + 1 < NIT) {
            av2 = *(const float4*)(Ap + (it + 1) * 8);
            wv2 = *(const float4*)(Wp + (it + 1) * 8);
            if (BNA) {
                float4 sc = *(const float4*)&g_scale[(it + 1) * 8 + lc];
                float4 sh = *(const float4*)&g_shift[(it + 1) * 8 + lc];
                av2.x = fmaxf(av2.x * sc.x + sh.x, 0.f);
                av2.y = fmaxf(av2.y * sc.y + sh.y, 0.f);
                av2.z = fmaxf(av2.z * sc.z + sh.z, 0.f);
                av2.w = fmaxf(av2.w * sc.w + sh.w, 0.f);
            }
        }
#pragma unroll
        for (int k = 0; k < 8; k++) {
            float4 a0 = *(const float4*)&As[cur][k * 132 + sa0];
            float4 a1 = *(const float4*)&As[cur][k * 132 + sa1];
            ulonglong2 bp0 = *(const ulonglong2*)&Bs[cur][k * 132 + sb0];
            ulonglong2 bp1 = *(const ulonglong2*)&Bs[cur][k * 132 + sb1];
            float a[8] = {a0.x, a0.y, a0.z, a0.w, a1.x, a1.y, a1.z, a1.w};
            ull bp[4] = {bp0.x, bp0.y, bp1.x, bp1.y};
#pragma unroll
            for (int i = 0; i < 8; i++) {
                ull as = splat2(a[i]);
#pragma unroll
                for (int j = 0; j < 4; j++) ffma2(acc2[i][j], as, bp[j]);
            }
        }
        if (it + 1 < NIT) {
            int nxt = 1 - cur;
            As[nxt][(lc + 0) * 132 + wp] = av2.x; As[nxt][(lc + 1) * 132 + wp] = av2.y;
            As[nxt][(lc + 2) * 132 + wp] = av2.z; As[nxt][(lc + 3) * 132 + wp] = av2.w;
            Bs[nxt][(lc + 0) * 132 + wp] = wv2.x; Bs[nxt][(lc + 1) * 132 + wp] = wv2.y;
            Bs[nxt][(lc + 2) * 132 + wp] = wv2.z; Bs[nxt][(lc + 3) * 132 + wp] = wv2.w;
            __syncthreads();
        }
    }
#pragma unroll
    for (int i = 0; i < 8; i++) {
        int r = brow + ty * 8 + i;
        float4* cp = (float4*)(C + (size_t)r * O + bcol + tx * 8);
        float2 p0 = unpk(acc2[i][0]), p1 = unpk(acc2[i][1]);
        float2 p2 = unpk(acc2[i][2]), p3 = unpk(acc2[i][3]);
        cp[0] = make_float4(p0.x, p0.y, p1.x, p1.y);
        cp[1] = make_float4(p2.x, p2.y, p3.x, p3.y);
    }
}

// ---------------- FUSED layer-2 GEMM (FFMA2 core) ----------------
template <int CIN, int STAGE>
__global__ __launch_bounds__(256) void gemm2_fused(const float* __restrict__ W) {
    const float* G = g_zbuf;
    const float* C = (STAGE == 0) ? g_c1out : g_c2out;
    const int* knn = (STAGE == 0) ? g_knn1 : g_knn2;
    constexpr int NPTS = (STAGE == 0) ? NN : S1V;
    constexpr int BSH = (STAGE == 0) ? 9 : 8;

    __shared__ float As[2][8 * 132];
    __shared__ float Bs[2][8 * 132];
    int tid = threadIdx.x;
    int brow = blockIdx.x * 128, bcol = blockIdx.y * 128;
    int tx = tid & 15, ty = tid >> 4;
    int lr = tid >> 1, lc = (tid & 1) * 4;

    int grow = brow + lr;
    int nb = knn[grow];
    int bs = grow >> 5;
    int b = bs >> BSH;
    const float* Gp = G + ((size_t)(b * NPTS + nb)) * CIN + lc;
    const float* Cp = C + (size_t)bs * CIN + lc;
    const float* Wp = W + (size_t)(bcol + lr) * CIN + lc;
    int wp = swz(lr);
    int sa0 = swz(ty * 8), sa1 = swz(ty * 8 + 4);
    int sb0 = swz(tx * 8), sb1 = swz(tx * 8 + 4);

    {
        float4 gv = *(const float4*)Gp;
        float4 cv = *(const float4*)Cp;
        float4 wv = *(const float4*)Wp;
        float4 sc = *(const float4*)&g_scale[lc];
        float4 sh = *(const float4*)&g_shift[lc];
        float ax = fmaxf((gv.x + cv.x) * sc.x + sh.x, 0.f);
        float ay = fmaxf((gv.y + cv.y) * sc.y + sh.y, 0.f);
        float az = fmaxf((gv.z + cv.z) * sc.z + sh.z, 0.f);
        float aw = fmaxf((gv.w + cv.w) * sc.w + sh.w, 0.f);
        As[0][(lc + 0) * 132 + wp] = ax; As[0][(lc + 1) * 132 + wp] = ay;
        As[0][(lc + 2) * 132 + wp] = az; As[0][(lc + 3) * 132 + wp] = aw;
        Bs[0][(lc + 0) * 132 + wp] = wv.x; Bs[0][(lc + 1) * 132 + wp] = wv.y;
        Bs[0][(lc + 2) * 132 + wp] = wv.z; Bs[0][(lc + 3) * 132 + wp] = wv.w;
    }
    __syncthreads();

    ull acc2[8][4];
#pragma unroll
    for (int i = 0; i < 8; i++)
#pragma unroll
        for (int j = 0; j < 4; j++) acc2[i][j] = 0ull;

    constexpr int NIT = CIN / 8;
#pragma unroll 2
    for (int it = 0; it < NIT; it++) {
        int cur = it & 1;
        float axp, ayp, azp, awp;
        float4 wv2;
        if (it + 1 < NIT) {
            float4 gv = *(const float4*)(Gp + (it + 1) * 8);
            float4 cv = *(const float4*)(Cp + (it + 1) * 8);
            wv2 = *(const float4*)(Wp + (it + 1) * 8);
            float4 sc = *(const float4*)&g_scale[(it + 1) * 8 + lc];
            float4 sh = *(const float4*)&g_shift[(it + 1) * 8 + lc];
            axp = fmaxf((gv.x + cv.x) * sc.x + sh.x, 0.f);
            ayp = fmaxf((gv.y + cv.y) * sc.y + sh.y, 0.f);
            azp = fmaxf((gv.z + cv.z) * sc.z + sh.z, 0.f);
            awp = fmaxf((gv.w + cv.w) * sc.w + sh.w, 0.f);
        }
#pragma unroll
        for (int k = 0; k < 8; k++) {
            float4 a0 = *(const float4*)&As[cur][k * 132 + sa0];
            float4 a1 = *(const float4*)&As[cur][k * 132 + sa1];
            ulonglong2 bp0 = *(const ulonglong2*)&Bs[cur][k * 132 + sb0];
            ulonglong2 bp1 = *(const ulonglong2*)&Bs[cur][k * 132 + sb1];
            float a[8] = {a0.x, a0.y, a0.z, a0.w, a1.x, a1.y, a1.z, a1.w};
            ull bp[4] = {bp0.x, bp0.y, bp1.x, bp1.y};
#pragma unroll
            for (int i = 0; i < 8; i++) {
                ull as = splat2(a[i]);
#pragma unroll
                for (int j = 0; j < 4; j++) ffma2(acc2[i][j], as, bp[j]);
            }
        }
        if (it + 1 < NIT) {
            int nxt = 1 - cur;
            As[nxt][(lc + 0) * 132 + wp] = axp; As[nxt][(lc + 1) * 132 + wp] = ayp;
            As[nxt][(lc + 2) * 132 + wp] = azp; As[nxt][(lc + 3) * 132 + wp] = awp;
            Bs[nxt][(lc + 0) * 132 + wp] = wv2.x; Bs[nxt][(lc + 1) * 132 + wp] = wv2.y;
            Bs[nxt][(lc + 2) * 132 + wp] = wv2.z; Bs[nxt][(lc + 3) * 132 + wp] = wv2.w;
            __syncthreads();
        }
    }

    float tmax[8], tmin[8], tsum[8], tsq[8];
#pragma unroll
    for (int j = 0; j < 8; j++) { tmax[j] = -1e30f; tmin[j] = 1e30f; tsum[j] = 0.f; tsq[j] = 0.f; }
#pragma unroll
    for (int i = 0; i < 8; i++)
#pragma unroll
        for (int jp = 0; jp < 4; jp++) {
            float2 p = unpk(acc2[i][jp]);
            int j0 = jp * 2;
            tmax[j0] = fmaxf(tmax[j0], p.x);
            tmin[j0] = fminf(tmin[j0], p.x);
            tsum[j0] += p.x;
            tsq[j0] += p.x * p.x;
            tmax[j0 + 1] = fmaxf(tmax[j0 + 1], p.y);
            tmin[j0 + 1] = fminf(tmin[j0 + 1], p.y);
            tsum[j0 + 1] += p.y;
            tsq[j0 + 1] += p.y * p.y;
        }

    float* redA = &As[0][0];
    float* redB = &Bs[0][0];
    __syncthreads();
#pragma unroll
    for (int j = 0; j < 8; j++) {
        redA[ty * 132 + tx * 8 + j] = tmax[j];
        redB[ty * 132 + tx * 8 + j] = tmin[j];
    }
    __syncthreads();
    {
        int ct = tid >> 6;
        int base = (tid & 63) * 2;
        int bs0 = brow >> 5;
#pragma unroll
        for (int u = 0; u < 2; u++) {
            int col = base + u;
            float m = -1e30f, mn = 1e30f;
#pragma unroll
            for (int v = 0; v < 4; v++) {
                m = fmaxf(m, redA[(ct * 4 + v) * 132 + col]);
                mn = fminf(mn, redB[(ct * 4 + v) * 132 + col]);
            }
            size_t o = (size_t)(bs0 + ct) * CIN + bcol + col;
            g_pmax[o] = m;
            g_pmin[o] = mn;
        }
    }
    __syncthreads();
#pragma unroll
    for (int j = 0; j < 8; j++) {
        redA[ty * 132 + tx * 8 + j] = tsum[j];
        redB[ty * 132 + tx * 8 + j] = tsq[j];
    }
    __syncthreads();
    if (tid < 128) {
        float s = 0.f;
#pragma unroll
        for (int v = 0; v < 16; v++) s += redA[v * 132 + tid];
        atomicAdd(&g_sum[bcol + tid], s);
    } else {
        int col = tid - 128;
        float s = 0.f;
#pragma unroll
        for (int v = 0; v < 16; v++) s += redB[v * 132 + col];
        atomicAdd(&g_sumsq[bcol + col], s);
    }
}

// ---------------- gather-stats for y = G[nb] + C[center] ----------------
template <int CIN, int STAGE>
__global__ void stats_gather_k(int R) {
    const float* G = g_zbuf;
    const float* C = (STAGE == 0) ? g_c1out : g_c2out;
    const int* knn = (STAGE == 0) ? g_knn1 : g_knn2;
    constexpr int NPTS = (STAGE == 0) ? NN : S1V;
    constexpr int BSH = (STAGE == 0) ? 9 : 8;
    constexpr int NSEG = CIN / 128;

    int wid = (blockIdx.x * blockDim.x + threadIdx.x) >> 5;
    int lane = threadIdx.x & 31;
    int nw = (gridDim.x * blockDim.x) >> 5;
    float s[NSEG][4], q[NSEG][4];
#pragma unroll
    for (int sg = 0; sg < NSEG; sg++)
#pragma unroll
        for (int j = 0; j < 4; j++) { s[sg][j] = 0.f; q[sg][j] = 0.f; }

    for (int row = wid; row < R; row += nw) {
        int nb = knn[row];
        int bs = row >> 5;
        int b = bs >> BSH;
        size_t gb = ((size_t)(b * NPTS + nb)) * CIN;
        size_t cb = (size_t)bs * CIN;
#pragma unroll
        for (int sg = 0; sg < NSEG; sg++) {
            int col = sg * 128 + lane * 4;
            float4 g = *(const float4*)(G + gb + col);
            float4 c = *(const float4*)(C + cb + col);
            float y0 = g.x + c.x, y1 = g.y + c.y, y2 = g.z + c.z, y3 = g.w + c.w;
            s[sg][0] += y0; s[sg][1] += y1; s[sg][2] += y2; s[sg][3] += y3;
            q[sg][0] += y0 * y0; q[sg][1] += y1 * y1; q[sg][2] += y2 * y2; q[sg][3] += y3 * y3;
        }
    }
    __shared__ float ss[CIN], sq[CIN];
    for (int t = threadIdx.x; t < CIN; t += 256) { ss[t] = 0.f; sq[t] = 0.f; }
    __syncthreads();
#pragma unroll
    for (int sg = 0; sg < NSEG; sg++)
#pragma unroll
        for (int j = 0; j < 4; j++) {
            atomicAdd(&ss[sg * 128 + lane * 4 + j], s[sg][j]);
            atomicAdd(&sq[sg * 128 + lane * 4 + j], q[sg][j]);
        }
    __syncthreads();
    for (int t = threadIdx.x; t < CIN; t += 256) {
        atomicAdd(&g_sum[t], ss[t]);
        atomicAdd(&g_sumsq[t], sq[t]);
    }
}

// ---------------- weight diffs ----------------
__global__ void wdiff1_k(const float* __restrict__ w) {
    int i = blockIdx.x * 256 + threadIdx.x;
    int o = i >> 6, d = i & 63;
    g_wdiff1[i] = w[o * 128 + 64 + d] - w[o * 128 + d];
}
__global__ void wdiff2_k(const float* __restrict__ w) {
    int i = blockIdx.x * 256 + threadIdx.x;
    int o = i >> 7, d = i & 127;
    g_wdiff2[i] = w[o * 256 + 128 + d] - w[o * 256 + d];
}

// ---------------- center feature gathers ----------------
__global__ void gather_cfeat1() {
    int i = blockIdx.x * 256 + threadIdx.x;
    int r = i >> 6, c = i & 63;
    int b = r >> 9;
    int fid = g_fidx1[r];
    float v = g_f[((size_t)(b * NN + fid)) * 64 + c];
    g_cfeat1[i] = fmaxf(v * g_scale[c] + g_shift[c], 0.f);
}
__global__ void gather_cfeat2() {
    int i = blockIdx.x * 256 + threadIdx.x;
    int r = i >> 7, c = i & 127;
    int b = r >> 8;
    int fid = g_fidx2[r];
    g_cfeat2[i] = g_f1[((size_t)(b * S1V + fid)) * 128 + c];
}

// ---------------- pool finish ----------------
__global__ void pool_finish1() {
    int i = blockIdx.x * 256 + threadIdx.x;
    int c = i & 127;
    float sc = g_scale[c];
    float v = (sc >= 0.f) ? g_pmax[i] : g_pmin[i];
    g_f1[i] = fmaxf(sc * v + g_shift[c], 0.f);
}
__global__ void pool_finish2(float* __restrict__ out) {
    int i = blockIdx.x * 256 + threadIdx.x;
    int bs = i >> 8, o = i & 255;
    int b = bs >> 8, s = bs & 255;
    float sc = g_scale[o];
    float v = (sc >= 0.f) ? g_pmax[i] : g_pmin[i];
    out[((size_t)(b * 256 + o)) * 256 + s] = fmaxf(sc * v + g_shift[o], 0.f);
}

// ---------------- launch sequence (dual-stream DAG) ----------------
extern "C" void kernel_launch(void* const* d_in, const int* in_sizes, int n_in,
                              void* d_out, int out_size) {
    const float* x     = (const float*)d_in[0];
    const float* w1    = (const float*)d_in[1];
    const float* w2    = (const float*)d_in[2];
    const float* g1    = (const float*)d_in[3];
    const float* b1    = (const float*)d_in[4];
    const float* g2    = (const float*)d_in[5];
    const float* b2    = (const float*)d_in[6];
    const float* s1w1  = (const float*)d_in[7];
    const float* s1w2  = (const float*)d_in[8];
    const float* s1g1  = (const float*)d_in[9];
    const float* s1b1  = (const float*)d_in[10];
    const float* s1g2  = (const float*)d_in[11];
    const float* s1b2  = (const float*)d_in[12];
    const float* s2w1  = (const float*)d_in[13];
    const float* s2w2  = (const float*)d_in[14];
    const float* s2g1  = (const float*)d_in[15];
    const float* s2b1  = (const float*)d_in[16];
    const float* s2g2  = (const float*)d_in[17];
    const float* s2b2  = (const float*)d_in[18];
    float* out = (float*)d_out;

    const int RP = BB * NN;
    const int R1 = BB * S1V * KV;
    const int R2 = BB * S2V * KV;

    // persistent side stream + events (created once; no device memory involved)
    static cudaStream_t s2s = nullptr;
    static cudaEvent_t ev_prep = nullptr, ev_fps1 = nullptr, ev_knn1 = nullptr,
                       ev_fps2 = nullptr, ev_knn2 = nullptr;
    if (!s2s) {
        cudaStreamCreateWithFlags(&s2s, cudaStreamNonBlocking);
        cudaEventCreateWithFlags(&ev_prep, cudaEventDisableTiming);
        cudaEventCreateWithFlags(&ev_fps1, cudaEventDisableTiming);
        cudaEventCreateWithFlags(&ev_knn1, cudaEventDisableTiming);
        cudaEventCreateWithFlags(&ev_fps2, cudaEventDisableTiming);
        cudaEventCreateWithFlags(&ev_knn2, cudaEventDisableTiming);
    }
    cudaStream_t m = 0;   // harness-captured (legacy) stream

    // --- main: coords ---
    prep_coords<<<RP / 256, 256, 0, m>>>(x);
    cudaEventRecord(ev_prep, m);

    // --- side stream: full sampling chain (coords only) ---
    cudaStreamWaitEvent(s2s, ev_prep, 0);
    fps_kernel<NN, S1V, 1024, 0><<<BB, 1024, 0, s2s>>>();
    cudaEventRecord(ev_fps1, s2s);
    gather_c2<<<BB * S1V / 256, 256, 0, s2s>>>();
    knn_kernel<NN, S1V, 0><<<BB * S1V / 4, 128, 0, s2s>>>();
    cudaEventRecord(ev_knn1, s2s);
    fps_kernel<S1V, S2V, 512, 1><<<BB, 512, 0, s2s>>>();
    cudaEventRecord(ev_fps2, s2s);
    knn_kernel<S1V, S2V, 1><<<BB * S2V / 4, 128, 0, s2s>>>();
    cudaEventRecord(ev_knn2, s2s);

    // --- main: feature chain (concurrent with sampling) ---
    cbr1_kernel<<<512, 256, 0, m>>>(x, w1);
    finalize_stats<<<1, 256, 0, m>>>(g1, b1, 1.0f / RP, 64);
    cbr2_kernel<<<512, 256, 0, m>>>(w2);
    finalize_stats<<<1, 256, 0, m>>>(g2, b2, 1.0f / RP, 64);

    // factored sg1 layer 1: G1 = bnrelu(f) @ w1a^T
    gemm_k<64, 128, true><<<dim3(512, 1), 256, 0, m>>>(2, s1w1, -1, 0, 128);
    wdiff1_k<<<128 * 64 / 256, 256, 0, m>>>(s1w1);
    cudaStreamWaitEvent(m, ev_fps1, 0);
    gather_cfeat1<<<BB * S1V * 64 / 256, 256, 0, m>>>();
    gemm_k<64, 64, false><<<dim3(64, 1), 256, 0, m>>>(3, nullptr, 7, 5, 128);

    cudaStreamWaitEvent(m, ev_knn1, 0);
    stats_gather_k<128, 0><<<512, 256, 0, m>>>(R1);
    finalize_stats<<<1, 256, 0, m>>>(s1g1, s1b1, 1.0f / R1, 128);

    gemm2_fused<128, 0><<<dim3(2048, 1), 256, 0, m>>>(s1w2);
    finalize_stats<<<1, 256, 0, m>>>(s1g2, s1b2, 1.0f / R1, 128);
    pool_finish1<<<BB * S1V * 128 / 256, 256, 0, m>>>();

    // factored sg2 layer 1: G2 = f1 @ w2a^T
    gemm_k<128, 256, false><<<dim3(64, 2), 256, 0, m>>>(9, s2w1, -1, 0, 256);
    wdiff2_k<<<256 * 128 / 256, 256, 0, m>>>(s2w1);
    cudaStreamWaitEvent(m, ev_fps2, 0);
    gather_cfeat2<<<BB * S2V * 128 / 256, 256, 0, m>>>();
    gemm_k<128, 128, false><<<dim3(32, 2), 256, 0, m>>>(4, nullptr, 8, 6, 256);

    cudaStreamWaitEvent(m, ev_knn2, 0);
    stats_gather_k<256, 1><<<512, 256, 0, m>>>(R2);
    finalize_stats<<<1, 256, 0, m>>>(s2g1, s2b1, 1.0f / R2, 256);

    gemm2_fused<256, 1><<<dim3(1024, 2), 256, 0, m>>>(s2w2);
    finalize_stats<<<1, 256, 0, m>>>(s2g2, s2b2, 1.0f / R2, 256);
    pool_finish2<<<BB * S2V * 256 / 256, 256, 0, m>>>(out);
}